// round 1
// baseline (speedup 1.0000x reference)
#include <cuda_runtime.h>

// Problem constants
constexpr int B_   = 2;
constexpr int S_   = 2048;
constexpr int Dm   = 1024;
constexpr int H_   = 16;
constexpr int DK_  = 64;
constexpr int Mrows = B_ * S_;        // 4096
constexpr float ATT_SCALE = 0.125f;   // 1/sqrt(64)

// Scratch (allocation-free: __device__ globals). 4 x 16 MB.
__device__ float g_Q[(size_t)Mrows * Dm];
__device__ float g_K[(size_t)Mrows * Dm];
__device__ float g_V[(size_t)Mrows * Dm];
__device__ float g_O[(size_t)Mrows * Dm];

// ---------------------------------------------------------------------------
// C[M,1024] = A[M,1024] @ W^T, W stored row-major [1024,1024] (row n = weights
// of output col n). Both operands K-contiguous -> coalesced loads.
// Tile 128x128x16, 256 threads, 8x8 per thread (split 4+4 to keep LDS.128
// fragment loads conflict-free).
// ---------------------------------------------------------------------------
__global__ __launch_bounds__(256) void sgemm_nt(const float* __restrict__ A,
                                                const float* __restrict__ Wt,
                                                float* __restrict__ C) {
    __shared__ float As[16][128];
    __shared__ float Bs[16][128];
    const int tid  = threadIdx.x;
    const int row0 = blockIdx.y * 128;
    const int col0 = blockIdx.x * 128;
    const int tx = tid & 15;
    const int ty = tid >> 4;
    const int lr = tid >> 2;   // 0..63
    const int lc = tid & 3;    // float4 index along k

    float acc[8][8];
#pragma unroll
    for (int i = 0; i < 8; ++i)
#pragma unroll
        for (int j = 0; j < 8; ++j) acc[i][j] = 0.f;

    for (int k0 = 0; k0 < Dm; k0 += 16) {
#pragma unroll
        for (int r = 0; r < 2; ++r) {
            const int m = lr + r * 64;
            float4 va = *(const float4*)(A  + (size_t)(row0 + m) * Dm + k0 + lc * 4);
            As[lc * 4 + 0][m] = va.x; As[lc * 4 + 1][m] = va.y;
            As[lc * 4 + 2][m] = va.z; As[lc * 4 + 3][m] = va.w;
            float4 vb = *(const float4*)(Wt + (size_t)(col0 + m) * Dm + k0 + lc * 4);
            Bs[lc * 4 + 0][m] = vb.x; Bs[lc * 4 + 1][m] = vb.y;
            Bs[lc * 4 + 2][m] = vb.z; Bs[lc * 4 + 3][m] = vb.w;
        }
        __syncthreads();
#pragma unroll
        for (int k = 0; k < 16; ++k) {
            float a[8], b[8];
            float4 t0 = *(const float4*)&As[k][ty * 4];
            float4 t1 = *(const float4*)&As[k][64 + ty * 4];
            a[0] = t0.x; a[1] = t0.y; a[2] = t0.z; a[3] = t0.w;
            a[4] = t1.x; a[5] = t1.y; a[6] = t1.z; a[7] = t1.w;
            float4 u0 = *(const float4*)&Bs[k][tx * 4];
            float4 u1 = *(const float4*)&Bs[k][64 + tx * 4];
            b[0] = u0.x; b[1] = u0.y; b[2] = u0.z; b[3] = u0.w;
            b[4] = u1.x; b[5] = u1.y; b[6] = u1.z; b[7] = u1.w;
#pragma unroll
            for (int i = 0; i < 8; ++i)
#pragma unroll
                for (int j = 0; j < 8; ++j) acc[i][j] += a[i] * b[j];
        }
        __syncthreads();
    }
#pragma unroll
    for (int i = 0; i < 8; ++i) {
        const int row = row0 + ((i < 4) ? (ty * 4 + i) : (64 + ty * 4 + (i - 4)));
        float4 v0 = make_float4(acc[i][0], acc[i][1], acc[i][2], acc[i][3]);
        float4 v1 = make_float4(acc[i][4], acc[i][5], acc[i][6], acc[i][7]);
        *(float4*)(C + (size_t)row * Dm + col0 + tx * 4)      = v0;
        *(float4*)(C + (size_t)row * Dm + col0 + 64 + tx * 4) = v1;
    }
}

// ---------------------------------------------------------------------------
// Flash attention: one CTA per (64-query tile, head, batch).
// smem: Qs[64][64] (scaled), Ks[64][68], Vs[64][64], Ss[64][68], Al[64].
// 256 threads: 16x16 grid, 4x4 micro-tile for both S=QK^T and O+=PV;
// online softmax handled by 4 threads/row + shfl reductions.
// ---------------------------------------------------------------------------
constexpr int QT = 64, KT = 64;
constexpr int KS_ST = 68, SS_ST = 68;
constexpr int SM_QS = 0;
constexpr int SM_KS = 4096;                // 64*64
constexpr int SM_VS = SM_KS + 64 * KS_ST;  // +4352 = 8448
constexpr int SM_SS = SM_VS + 4096;        // 12544
constexpr int SM_AL = SM_SS + 64 * SS_ST;  // 16896
constexpr int SM_FLOATS = SM_AL + 64;      // 16960
constexpr int SM_BYTES  = SM_FLOATS * 4;   // 67840

__global__ __launch_bounds__(256) void flash_attn(const float* __restrict__ Q,
                                                  const float* __restrict__ K,
                                                  const float* __restrict__ V,
                                                  float* __restrict__ O) {
    extern __shared__ float sm[];
    float* Qs = sm + SM_QS;
    float* Ks = sm + SM_KS;
    float* Vs = sm + SM_VS;
    float* Ss = sm + SM_SS;
    float* Al = sm + SM_AL;

    const int tid = threadIdx.x;
    const int q0  = blockIdx.x * QT;
    const int h   = blockIdx.y;
    const int b   = blockIdx.z;

    const float* Qb = Q + ((size_t)(b * S_ + q0)) * Dm + h * DK_;
    const float* Kb = K + ((size_t)b * S_) * Dm + h * DK_;
    const float* Vb = V + ((size_t)b * S_) * Dm + h * DK_;

    // Load Q tile (pre-scaled)
#pragma unroll
    for (int it = 0; it < 4; ++it) {
        const int id4 = tid + it * 256;
        const int r = id4 >> 4, c4 = id4 & 15;
        float4 v = *(const float4*)(Qb + (size_t)r * Dm + c4 * 4);
        v.x *= ATT_SCALE; v.y *= ATT_SCALE; v.z *= ATT_SCALE; v.w *= ATT_SCALE;
        *(float4*)(Qs + r * 64 + c4 * 4) = v;
    }

    const int tx = tid & 15, ty = tid >> 4;
    const int qy = ty * 4, kx = tx * 4;
    const int srow = tid >> 2, sub = tid & 3;

    float acc[4][4];
#pragma unroll
    for (int i = 0; i < 4; ++i)
#pragma unroll
        for (int j = 0; j < 4; ++j) acc[i][j] = 0.f;
    float m_r = -1e30f, l_r = 0.f;

    for (int kt = 0; kt < S_ / KT; ++kt) {
        __syncthreads();
        // Load K (padded stride) + V tiles
#pragma unroll
        for (int it = 0; it < 4; ++it) {
            const int id4 = tid + it * 256;
            const int r = id4 >> 4, c4 = id4 & 15;
            float4 kv = *(const float4*)(Kb + (size_t)(kt * KT + r) * Dm + c4 * 4);
            *(float4*)(Ks + r * KS_ST + c4 * 4) = kv;
            float4 vv = *(const float4*)(Vb + (size_t)(kt * KT + r) * Dm + c4 * 4);
            *(float4*)(Vs + r * 64 + c4 * 4) = vv;
        }
        __syncthreads();

        // S = Qs @ Ks^T   (64x64x64)
        float s[4][4];
#pragma unroll
        for (int i = 0; i < 4; ++i)
#pragma unroll
            for (int j = 0; j < 4; ++j) s[i][j] = 0.f;
        for (int d0 = 0; d0 < DK_; d0 += 4) {
            float a[4][4], bb[4][4];
#pragma unroll
            for (int i = 0; i < 4; ++i) {
                float4 v = *(const float4*)(Qs + (qy + i) * 64 + d0);
                a[i][0] = v.x; a[i][1] = v.y; a[i][2] = v.z; a[i][3] = v.w;
            }
#pragma unroll
            for (int j = 0; j < 4; ++j) {
                float4 v = *(const float4*)(Ks + (kx + j) * KS_ST + d0);
                bb[j][0] = v.x; bb[j][1] = v.y; bb[j][2] = v.z; bb[j][3] = v.w;
            }
#pragma unroll
            for (int t = 0; t < 4; ++t)
#pragma unroll
                for (int i = 0; i < 4; ++i)
#pragma unroll
                    for (int j = 0; j < 4; ++j) s[i][j] += a[i][t] * bb[j][t];
        }
#pragma unroll
        for (int i = 0; i < 4; ++i)
#pragma unroll
            for (int j = 0; j < 4; ++j)
                Ss[(qy + i) * SS_ST + kx + j] = s[i][j];
        __syncthreads();

        // Online softmax (4 threads per row; identical l/m in all 4 lanes)
        {
            float* roww = Ss + srow * SS_ST + sub * 16;
            float tmax = -1e30f;
#pragma unroll
            for (int c = 0; c < 16; ++c) tmax = fmaxf(tmax, roww[c]);
            tmax = fmaxf(tmax, __shfl_xor_sync(0xffffffffu, tmax, 1));
            tmax = fmaxf(tmax, __shfl_xor_sync(0xffffffffu, tmax, 2));
            const float mnew = fmaxf(m_r, tmax);
            const float al = __expf(m_r - mnew);
            float lsum = 0.f;
#pragma unroll
            for (int c = 0; c < 16; ++c) {
                const float p = __expf(roww[c] - mnew);
                roww[c] = p;
                lsum += p;
            }
            lsum += __shfl_xor_sync(0xffffffffu, lsum, 1);
            lsum += __shfl_xor_sync(0xffffffffu, lsum, 2);
            l_r = l_r * al + lsum;
            m_r = mnew;
            if (sub == 0) Al[srow] = al;
        }
        __syncthreads();

        // O = al*O + P @ V  (64x64x64)
        float al4[4];
#pragma unroll
        for (int i = 0; i < 4; ++i) al4[i] = Al[qy + i];
#pragma unroll
        for (int i = 0; i < 4; ++i)
#pragma unroll
            for (int j = 0; j < 4; ++j) acc[i][j] *= al4[i];
        for (int k0 = 0; k0 < KT; k0 += 4) {
            float a[4][4], bb[4][4];
#pragma unroll
            for (int i = 0; i < 4; ++i) {
                float4 v = *(const float4*)(Ss + (qy + i) * SS_ST + k0);
                a[i][0] = v.x; a[i][1] = v.y; a[i][2] = v.z; a[i][3] = v.w;
            }
#pragma unroll
            for (int t = 0; t < 4; ++t) {
                float4 v = *(const float4*)(Vs + (k0 + t) * 64 + kx);
                bb[t][0] = v.x; bb[t][1] = v.y; bb[t][2] = v.z; bb[t][3] = v.w;
            }
#pragma unroll
            for (int t = 0; t < 4; ++t)
#pragma unroll
                for (int i = 0; i < 4; ++i)
#pragma unroll
                    for (int j = 0; j < 4; ++j) acc[i][j] += a[i][t] * bb[t][j];
        }
    }

    // Epilogue: divide by l and store to [B,S,D] layout
    __syncthreads();
    if (sub == 0) Al[srow] = 1.0f / l_r;
    __syncthreads();
#pragma unroll
    for (int i = 0; i < 4; ++i) {
        const float inv = Al[qy + i];
        float4 v = make_float4(acc[i][0] * inv, acc[i][1] * inv,
                               acc[i][2] * inv, acc[i][3] * inv);
        *(float4*)(O + ((size_t)(b * S_ + q0 + qy + i)) * Dm + h * DK_ + kx) = v;
    }
}

// ---------------------------------------------------------------------------
extern "C" void kernel_launch(void* const* d_in, const int* in_sizes, int n_in,
                              void* d_out, int out_size) {
    const float* x  = (const float*)d_in[0];
    const float* Wq = (const float*)d_in[1];
    const float* Wk = (const float*)d_in[2];
    const float* Wv = (const float*)d_in[3];
    const float* Wo = (const float*)d_in[4];
    float* out = (float*)d_out;

    float *Qp, *Kp, *Vp, *Op;
    cudaGetSymbolAddress((void**)&Qp, g_Q);
    cudaGetSymbolAddress((void**)&Kp, g_K);
    cudaGetSymbolAddress((void**)&Vp, g_V);
    cudaGetSymbolAddress((void**)&Op, g_O);

    cudaFuncSetAttribute(flash_attn, cudaFuncAttributeMaxDynamicSharedMemorySize,
                         SM_BYTES);

    const dim3 gProj(Dm / 128, Mrows / 128);  // (8, 32)
    sgemm_nt<<<gProj, 256>>>(x, Wq, Qp);
    sgemm_nt<<<gProj, 256>>>(x, Wk, Kp);
    sgemm_nt<<<gProj, 256>>>(x, Wv, Vp);

    const dim3 gAttn(S_ / QT, H_, B_);        // (32, 16, 2)
    flash_attn<<<gAttn, 256, SM_BYTES>>>(Qp, Kp, Vp, Op);

    sgemm_nt<<<gProj, 256>>>(Op, Wo, out);
}

// round 3
// speedup vs baseline: 2.5837x; 2.5837x over previous
#include <cuda_runtime.h>
#include <cuda_bf16.h>
#include <cstdint>

// ===========================================================================
// Problem constants
// ===========================================================================
constexpr int B_   = 2;
constexpr int S_   = 2048;
constexpr int Dm   = 1024;
constexpr int H_   = 16;
constexpr int DK_  = 64;
constexpr int Mrows = B_ * S_;        // 4096
constexpr float ATT_SCALE = 0.125f;   // 1/sqrt(64)

// Scratch (allocation-free: __device__ globals). 4 x 16 MB.
__device__ float g_Q[(size_t)Mrows * Dm];
__device__ float g_K[(size_t)Mrows * Dm];
__device__ float g_V[(size_t)Mrows * Dm];
__device__ float g_O[(size_t)Mrows * Dm];

// ===========================================================================
// mma.sync / ldmatrix helpers (legacy tensor path — compiles on sm_103 base)
// ===========================================================================
#define MMA_BF16(c, a, b0, b1)                                              \
    asm volatile(                                                           \
        "mma.sync.aligned.m16n8k16.row.col.f32.bf16.bf16.f32 "              \
        "{%0,%1,%2,%3},{%4,%5,%6,%7},{%8,%9},{%0,%1,%2,%3};"                \
        : "+f"((c)[0]), "+f"((c)[1]), "+f"((c)[2]), "+f"((c)[3])            \
        : "r"((a)[0]), "r"((a)[1]), "r"((a)[2]), "r"((a)[3]),               \
          "r"(b0), "r"(b1))

#define MMA_TF32(c, a, b0, b1)                                              \
    asm volatile(                                                           \
        "mma.sync.aligned.m16n8k8.row.col.f32.tf32.tf32.f32 "               \
        "{%0,%1,%2,%3},{%4,%5,%6,%7},{%8,%9},{%0,%1,%2,%3};"                \
        : "+f"((c)[0]), "+f"((c)[1]), "+f"((c)[2]), "+f"((c)[3])            \
        : "r"((a)[0]), "r"((a)[1]), "r"((a)[2]), "r"((a)[3]),               \
          "r"(b0), "r"(b1))

#define LDSM4(R, addr)                                                      \
    asm volatile("ldmatrix.sync.aligned.m8n8.x4.shared.b16 "                \
                 "{%0,%1,%2,%3}, [%4];"                                     \
                 : "=r"((R)[0]), "=r"((R)[1]), "=r"((R)[2]), "=r"((R)[3])   \
                 : "r"(addr))

__device__ __forceinline__ uint32_t smem_u32(const void* p) {
    uint32_t a;
    asm("{ .reg .u64 t; cvta.to.shared.u64 t, %1; cvt.u32.u64 %0, t; }"
        : "=r"(a) : "l"(p));
    return a;
}
__device__ __forceinline__ uint32_t f2tf(float x) {
    uint32_t r;
    asm("cvt.rna.tf32.f32 %0, %1;" : "=r"(r) : "f"(x));
    return r;
}
__device__ __forceinline__ float u2f(uint32_t x) { return __uint_as_float(x); }
__device__ __forceinline__ uint32_t f_as_u(float x) { return __float_as_uint(x); }

// Split two fp32 into packed bf16x2 hi + bf16x2 lo (hi 8 bits + next 8 bits).
__device__ __forceinline__ void split2(float x, float y, uint32_t& hi, uint32_t& lo) {
    __nv_bfloat16 hx = __float2bfloat16_rn(x);
    __nv_bfloat16 hy = __float2bfloat16_rn(y);
    float rx = x - __bfloat162float(hx);
    float ry = y - __bfloat162float(hy);
    __nv_bfloat16 lx = __float2bfloat16_rn(rx);
    __nv_bfloat16 ly = __float2bfloat16_rn(ry);
    hi = ((uint32_t)__bfloat16_as_ushort(hy) << 16) | (uint32_t)__bfloat16_as_ushort(hx);
    lo = ((uint32_t)__bfloat16_as_ushort(ly) << 16) | (uint32_t)__bfloat16_as_ushort(lx);
}

// ===========================================================================
// GEMM: C[4096,1024] = A @ W^T via bf16 3-term split mma.sync.
// CTA tile 128x128, K-chunk 32, double-buffered smem bf16 (hi|lo).
// smem per buffer: Ahi 8K | Alo 8K | Bhi 8K | Blo 8K = 32KB; x2 = 64KB.
// Row layout: 128 rows x 64B (32 bf16); 16B chunks XOR-swizzled:
//   phys_chunk = chunk ^ ((row>>1)&3)  -> conflict-free ldmatrix.
// ===========================================================================
constexpr int KC  = 32;
constexpr int NKC = Dm / KC;   // 32
constexpr int GEMM_SMEM = 65536;

__device__ __forceinline__ uint32_t swaddr(uint32_t base, int row, int ch) {
    return base + row * 64 + (((ch) ^ ((row >> 1) & 3)) << 4);
}

__device__ __forceinline__ void stage_store(char* hiBase, char* loBase, int row, int ch,
                                            float4 v0, float4 v1) {
    uint4 hi, lo;
    split2(v0.x, v0.y, hi.x, lo.x);
    split2(v0.z, v0.w, hi.y, lo.y);
    split2(v1.x, v1.y, hi.z, lo.z);
    split2(v1.z, v1.w, hi.w, lo.w);
    const uint32_t off = row * 64 + (((ch) ^ ((row >> 1) & 3)) << 4);
    *(uint4*)(hiBase + off) = hi;
    *(uint4*)(loBase + off) = lo;
}

__global__ __launch_bounds__(256) void gemm_bf16s(const float* __restrict__ A,
                                                  const float* __restrict__ W,
                                                  float* __restrict__ C) {
    extern __shared__ char smc[];
    const uint32_t smb = smem_u32(smc);
    const int tid = threadIdx.x;
    const int lane = tid & 31;
    const int wid = tid >> 5;
    const int row0 = blockIdx.y * 128;
    const int col0 = blockIdx.x * 128;
    const int wm = (wid >> 2) * 64;     // warp m offset (2 rows of warps)
    const int wn = (wid & 3) * 32;      // warp n offset (4 cols of warps)
    const int group = lane >> 2, tig = lane & 3;

    float c[4][4][4];
#pragma unroll
    for (int i = 0; i < 4; ++i)
#pragma unroll
        for (int j = 0; j < 4; ++j)
#pragma unroll
            for (int r = 0; r < 4; ++r) c[i][j][r] = 0.f;

    // loader mapping: thread -> (row, k-half of 16 floats)
    const int lr = tid >> 1, lh = tid & 1;
    const float* pa = A + (size_t)(row0 + lr) * Dm + lh * 16;
    const float* pw = W + (size_t)(col0 + lr) * Dm + lh * 16;

    // prologue: k-chunk 0 -> buffer 0
    {
        float4 ra0 = *(const float4*)(pa + 0),  ra1 = *(const float4*)(pa + 4);
        float4 ra2 = *(const float4*)(pa + 8),  ra3 = *(const float4*)(pa + 12);
        float4 rb0 = *(const float4*)(pw + 0),  rb1 = *(const float4*)(pw + 4);
        float4 rb2 = *(const float4*)(pw + 8),  rb3 = *(const float4*)(pw + 12);
        char* bA = smc;
        char* bB = smc + 16384;
        stage_store(bA, bA + 8192, lr, lh * 2 + 0, ra0, ra1);
        stage_store(bA, bA + 8192, lr, lh * 2 + 1, ra2, ra3);
        stage_store(bB, bB + 8192, lr, lh * 2 + 0, rb0, rb1);
        stage_store(bB, bB + 8192, lr, lh * 2 + 1, rb2, rb3);
    }
    __syncthreads();

    for (int kc = 0; kc < NKC; ++kc) {
        float4 ra0, ra1, ra2, ra3, rb0, rb1, rb2, rb3;
        if (kc + 1 < NKC) {
            const float* qa = pa + (kc + 1) * KC;
            const float* qw = pw + (kc + 1) * KC;
            ra0 = *(const float4*)(qa + 0);  ra1 = *(const float4*)(qa + 4);
            ra2 = *(const float4*)(qa + 8);  ra3 = *(const float4*)(qa + 12);
            rb0 = *(const float4*)(qw + 0);  rb1 = *(const float4*)(qw + 4);
            rb2 = *(const float4*)(qw + 8);  rb3 = *(const float4*)(qw + 12);
        }

        const uint32_t sA = smb + (kc & 1) * 32768;        // A hi
        const uint32_t sB = sA + 16384;                    // B hi
#pragma unroll
        for (int u = 0; u < 2; ++u) {                      // two k16 steps
            uint32_t bh[8], bl8[8];
#pragma unroll
            for (int p = 0; p < 2; ++p) {
                const int nrow = wn + p * 16 + (lane & 15);
                const int chL = u * 2 + (lane >> 4);
                LDSM4(bh + p * 4,  swaddr(sB,        nrow, chL));
                LDSM4(bl8 + p * 4, swaddr(sB + 8192, nrow, chL));
            }
#pragma unroll
            for (int mt = 0; mt < 4; ++mt) {
                const int mrow = wm + mt * 16 + (lane & 15);
                const int chL = u * 2 + (lane >> 4);
                uint32_t ah[4], alr[4];
                LDSM4(ah,  swaddr(sA,        mrow, chL));
                LDSM4(alr, swaddr(sA + 8192, mrow, chL));
#pragma unroll
                for (int j = 0; j < 4; ++j) {
                    const int p = j >> 1, q = j & 1;
                    MMA_BF16(c[mt][j], ah,  bh[p * 4 + q],  bh[p * 4 + q + 2]);
                    MMA_BF16(c[mt][j], ah,  bl8[p * 4 + q], bl8[p * 4 + q + 2]);
                    MMA_BF16(c[mt][j], alr, bh[p * 4 + q],  bh[p * 4 + q + 2]);
                }
            }
        }

        if (kc + 1 < NKC) {
            char* bA = smc + ((kc + 1) & 1) * 32768;
            char* bB = bA + 16384;
            stage_store(bA, bA + 8192, lr, lh * 2 + 0, ra0, ra1);
            stage_store(bA, bA + 8192, lr, lh * 2 + 1, ra2, ra3);
            stage_store(bB, bB + 8192, lr, lh * 2 + 0, rb0, rb1);
            stage_store(bB, bB + 8192, lr, lh * 2 + 1, rb2, rb3);
        }
        __syncthreads();
    }

    // epilogue
#pragma unroll
    for (int mt = 0; mt < 4; ++mt) {
#pragma unroll
        for (int j = 0; j < 4; ++j) {
            const int r = row0 + wm + mt * 16 + group;
            const int col = col0 + wn + j * 8 + tig * 2;
            float2 v0 = make_float2(c[mt][j][0], c[mt][j][1]);
            float2 v1 = make_float2(c[mt][j][2], c[mt][j][3]);
            *(float2*)(C + (size_t)r * Dm + col)       = v0;
            *(float2*)(C + (size_t)(r + 8) * Dm + col) = v1;
        }
    }
}

// ===========================================================================
// Flash attention with tf32 mma.sync.
// CTA = 128 q-rows x (head, batch); 8 warps, each owns 16 q-rows.
// Q fragments resident in registers (cvt.rna.tf32, pre-scaled).
// K tile 64x64 -> Ks (stride 68), V tile -> Vs (stride 72), both cvt'd tf32.
// S fragments softmaxed in registers; P stored to warp-private Ss rows
// (stride 68) and re-fragmented for PV.
// ===========================================================================
constexpr int KS_ST = 68, VS_ST = 72, SS_ST = 68;
constexpr int OFF_KS = 0;
constexpr int OFF_VS = 64 * KS_ST;              // 4352
constexpr int OFF_SS = OFF_VS + 64 * VS_ST;     // 8960
constexpr int ATT_SMEM_FLOATS = OFF_SS + 128 * SS_ST;  // 17664
constexpr int ATT_SMEM = ATT_SMEM_FLOATS * 4;          // 70656 B

__global__ __launch_bounds__(256) void flash_tf32(const float* __restrict__ Q,
                                                  const float* __restrict__ K,
                                                  const float* __restrict__ V,
                                                  float* __restrict__ O) {
    extern __shared__ float smf[];
    float* Ks = smf + OFF_KS;
    float* Vs = smf + OFF_VS;
    float* Ss = smf + OFF_SS;

    const int tid = threadIdx.x;
    const int lane = tid & 31;
    const int wid = tid >> 5;
    const int group = lane >> 2, tig = lane & 3;
    const int q0 = blockIdx.x * 128;
    const int h = blockIdx.y;
    const int b = blockIdx.z;
    const int wb = wid * 16;

    // Resident Q fragments (scaled + tf32-rounded)
    uint32_t qf[8][4];
    {
        const float* Qb = Q + ((size_t)(b * S_ + q0 + wb)) * Dm + h * DK_;
#pragma unroll
        for (int ks = 0; ks < 8; ++ks) {
            const int k0 = ks * 8 + tig;
            qf[ks][0] = f2tf(Qb[(size_t)group * Dm + k0] * ATT_SCALE);
            qf[ks][1] = f2tf(Qb[(size_t)(group + 8) * Dm + k0] * ATT_SCALE);
            qf[ks][2] = f2tf(Qb[(size_t)group * Dm + k0 + 4] * ATT_SCALE);
            qf[ks][3] = f2tf(Qb[(size_t)(group + 8) * Dm + k0 + 4] * ATT_SCALE);
        }
    }

    float of[8][4];
#pragma unroll
    for (int nt = 0; nt < 8; ++nt)
#pragma unroll
        for (int r = 0; r < 4; ++r) of[nt][r] = 0.f;
    float m0 = -1e30f, m1 = -1e30f, l0 = 0.f, l1 = 0.f;

    const float* Kb = K + ((size_t)(b * S_)) * Dm + h * DK_;
    const float* Vb = V + ((size_t)(b * S_)) * Dm + h * DK_;

    for (int kt = 0; kt < S_ / 64; ++kt) {
        __syncthreads();   // all warps done reading previous Ks/Vs
        // cooperative load + tf32 cvt of K and V tiles (64 x 64 each)
#pragma unroll
        for (int i = 0; i < 4; ++i) {
            const int id = tid + i * 256;
            const int r = id >> 4, c4 = (id & 15) * 4;
            float4 kv = *(const float4*)(Kb + (size_t)(kt * 64 + r) * Dm + c4);
            float4 ko = make_float4(u2f(f2tf(kv.x)), u2f(f2tf(kv.y)),
                                    u2f(f2tf(kv.z)), u2f(f2tf(kv.w)));
            *(float4*)(Ks + r * KS_ST + c4) = ko;
            float4 vv = *(const float4*)(Vb + (size_t)(kt * 64 + r) * Dm + c4);
            float4 vo = make_float4(u2f(f2tf(vv.x)), u2f(f2tf(vv.y)),
                                    u2f(f2tf(vv.z)), u2f(f2tf(vv.w)));
            *(float4*)(Vs + r * VS_ST + c4) = vo;
        }
        __syncthreads();

        // S = Q K^T (16 x 64 per warp)
        float sf[8][4];
#pragma unroll
        for (int nt = 0; nt < 8; ++nt)
#pragma unroll
            for (int r = 0; r < 4; ++r) sf[nt][r] = 0.f;
#pragma unroll
        for (int nt = 0; nt < 8; ++nt) {
            const float* krow = Ks + (nt * 8 + group) * KS_ST;
#pragma unroll
            for (int ks = 0; ks < 8; ++ks) {
                const uint32_t b0 = f_as_u(krow[ks * 8 + tig]);
                const uint32_t b1 = f_as_u(krow[ks * 8 + tig + 4]);
                MMA_TF32(sf[nt], qf[ks], b0, b1);
            }
        }

        // online softmax on fragments
        float mx0 = -1e30f, mx1 = -1e30f;
#pragma unroll
        for (int nt = 0; nt < 8; ++nt) {
            mx0 = fmaxf(mx0, fmaxf(sf[nt][0], sf[nt][1]));
            mx1 = fmaxf(mx1, fmaxf(sf[nt][2], sf[nt][3]));
        }
        mx0 = fmaxf(mx0, __shfl_xor_sync(0xffffffffu, mx0, 1));
        mx0 = fmaxf(mx0, __shfl_xor_sync(0xffffffffu, mx0, 2));
        mx1 = fmaxf(mx1, __shfl_xor_sync(0xffffffffu, mx1, 1));
        mx1 = fmaxf(mx1, __shfl_xor_sync(0xffffffffu, mx1, 2));
        const float M0 = fmaxf(m0, mx0), M1 = fmaxf(m1, mx1);
        const float al0 = __expf(m0 - M0), al1 = __expf(m1 - M1);
        float s0 = 0.f, s1 = 0.f;
#pragma unroll
        for (int nt = 0; nt < 8; ++nt) {
            sf[nt][0] = __expf(sf[nt][0] - M0);
            sf[nt][1] = __expf(sf[nt][1] - M0);
            sf[nt][2] = __expf(sf[nt][2] - M1);
            sf[nt][3] = __expf(sf[nt][3] - M1);
            s0 += sf[nt][0] + sf[nt][1];
            s1 += sf[nt][2] + sf[nt][3];
        }
        s0 += __shfl_xor_sync(0xffffffffu, s0, 1);
        s0 += __shfl_xor_sync(0xffffffffu, s0, 2);
        s1 += __shfl_xor_sync(0xffffffffu, s1, 1);
        s1 += __shfl_xor_sync(0xffffffffu, s1, 2);
        l0 = l0 * al0 + s0;  m0 = M0;
        l1 = l1 * al1 + s1;  m1 = M1;

        // store P (tf32-rounded) to warp-private Ss rows
#pragma unroll
        for (int nt = 0; nt < 8; ++nt) {
            float2 p0 = make_float2(u2f(f2tf(sf[nt][0])), u2f(f2tf(sf[nt][1])));
            float2 p1 = make_float2(u2f(f2tf(sf[nt][2])), u2f(f2tf(sf[nt][3])));
            *(float2*)(Ss + (wb + group) * SS_ST + nt * 8 + tig * 2)     = p0;
            *(float2*)(Ss + (wb + group + 8) * SS_ST + nt * 8 + tig * 2) = p1;
        }
        __syncwarp();

        // rescale O, then O += P V
#pragma unroll
        for (int nt = 0; nt < 8; ++nt) {
            of[nt][0] *= al0; of[nt][1] *= al0;
            of[nt][2] *= al1; of[nt][3] *= al1;
        }
#pragma unroll
        for (int ks = 0; ks < 8; ++ks) {
            uint32_t pa[4];
            pa[0] = f_as_u(Ss[(wb + group) * SS_ST + ks * 8 + tig]);
            pa[1] = f_as_u(Ss[(wb + group + 8) * SS_ST + ks * 8 + tig]);
            pa[2] = f_as_u(Ss[(wb + group) * SS_ST + ks * 8 + tig + 4]);
            pa[3] = f_as_u(Ss[(wb + group + 8) * SS_ST + ks * 8 + tig + 4]);
            const float* v0row = Vs + (ks * 8 + tig) * VS_ST;
            const float* v1row = Vs + (ks * 8 + tig + 4) * VS_ST;
#pragma unroll
            for (int nt = 0; nt < 8; ++nt) {
                const uint32_t b0 = f_as_u(v0row[nt * 8 + group]);
                const uint32_t b1 = f_as_u(v1row[nt * 8 + group]);
                MMA_TF32(of[nt], pa, b0, b1);
            }
        }
    }

    // epilogue
    const float i0 = 1.f / l0, i1 = 1.f / l1;
    float* Ob = O + ((size_t)(b * S_ + q0 + wb)) * Dm + h * DK_;
#pragma unroll
    for (int nt = 0; nt < 8; ++nt) {
        float2 v0 = make_float2(of[nt][0] * i0, of[nt][1] * i0);
        float2 v1 = make_float2(of[nt][2] * i1, of[nt][3] * i1);
        *(float2*)(Ob + (size_t)group * Dm + nt * 8 + tig * 2)       = v0;
        *(float2*)(Ob + (size_t)(group + 8) * Dm + nt * 8 + tig * 2) = v1;
    }
}

// ===========================================================================
extern "C" void kernel_launch(void* const* d_in, const int* in_sizes, int n_in,
                              void* d_out, int out_size) {
    const float* x  = (const float*)d_in[0];
    const float* Wq = (const float*)d_in[1];
    const float* Wk = (const float*)d_in[2];
    const float* Wv = (const float*)d_in[3];
    const float* Wo = (const float*)d_in[4];
    float* out = (float*)d_out;

    float *Qp, *Kp, *Vp, *Op;
    cudaGetSymbolAddress((void**)&Qp, g_Q);
    cudaGetSymbolAddress((void**)&Kp, g_K);
    cudaGetSymbolAddress((void**)&Vp, g_V);
    cudaGetSymbolAddress((void**)&Op, g_O);

    cudaFuncSetAttribute(gemm_bf16s, cudaFuncAttributeMaxDynamicSharedMemorySize,
                         GEMM_SMEM);
    cudaFuncSetAttribute(flash_tf32, cudaFuncAttributeMaxDynamicSharedMemorySize,
                         ATT_SMEM);

    const dim3 gProj(Dm / 128, Mrows / 128);      // (8, 32)
    gemm_bf16s<<<gProj, 256, GEMM_SMEM>>>(x, Wq, Qp);
    gemm_bf16s<<<gProj, 256, GEMM_SMEM>>>(x, Wk, Kp);
    gemm_bf16s<<<gProj, 256, GEMM_SMEM>>>(x, Wv, Vp);

    const dim3 gAttn(S_ / 128, H_, B_);           // (16, 16, 2)
    flash_tf32<<<gAttn, 256, ATT_SMEM>>>(Qp, Kp, Vp, Op);

    gemm_bf16s<<<gProj, 256, GEMM_SMEM>>>(Op, Wo, out);
}

// round 6
// speedup vs baseline: 3.5579x; 1.3770x over previous
#include <cuda_runtime.h>
#include <cuda_bf16.h>
#include <cstdint>

// ===========================================================================
// Problem constants
// ===========================================================================
constexpr int B_   = 2;
constexpr int S_   = 2048;
constexpr int Dm   = 1024;
constexpr int H_   = 16;
constexpr int DK_  = 64;
constexpr int Mrows = B_ * S_;        // 4096
constexpr float ATT_SCALE = 0.125f;   // 1/sqrt(64)

// Scratch (allocation-free: __device__ globals)
__device__ float g_Q[(size_t)Mrows * Dm];
__device__ float g_K[(size_t)Mrows * Dm];
__device__ float g_V[(size_t)Mrows * Dm];
__device__ float g_O[(size_t)Mrows * Dm];
__device__ __nv_bfloat16 g_xh[(size_t)Mrows * Dm];
__device__ __nv_bfloat16 g_xl[(size_t)Mrows * Dm];
__device__ __nv_bfloat16 g_oh[(size_t)Mrows * Dm];
__device__ __nv_bfloat16 g_ol[(size_t)Mrows * Dm];
__device__ __nv_bfloat16 g_wh[(size_t)4 * Dm * Dm];
__device__ __nv_bfloat16 g_wl[(size_t)4 * Dm * Dm];

// ===========================================================================
// mma.sync / ldmatrix / cp.async helpers (legacy tensor path, sm_103 base)
// ===========================================================================
#define MMA_BF16(c, a, b0, b1)                                              \
    asm volatile(                                                           \
        "mma.sync.aligned.m16n8k16.row.col.f32.bf16.bf16.f32 "              \
        "{%0,%1,%2,%3},{%4,%5,%6,%7},{%8,%9},{%0,%1,%2,%3};"                \
        : "+f"((c)[0]), "+f"((c)[1]), "+f"((c)[2]), "+f"((c)[3])            \
        : "r"((a)[0]), "r"((a)[1]), "r"((a)[2]), "r"((a)[3]),               \
          "r"(b0), "r"(b1))

#define MMA_TF32(c, a, b0, b1)                                              \
    asm volatile(                                                           \
        "mma.sync.aligned.m16n8k8.row.col.f32.tf32.tf32.f32 "               \
        "{%0,%1,%2,%3},{%4,%5,%6,%7},{%8,%9},{%0,%1,%2,%3};"                \
        : "+f"((c)[0]), "+f"((c)[1]), "+f"((c)[2]), "+f"((c)[3])            \
        : "r"((a)[0]), "r"((a)[1]), "r"((a)[2]), "r"((a)[3]),               \
          "r"(b0), "r"(b1))

#define LDSM4(R, addr)                                                      \
    asm volatile("ldmatrix.sync.aligned.m8n8.x4.shared.b16 "                \
                 "{%0,%1,%2,%3}, [%4];"                                     \
                 : "=r"((R)[0]), "=r"((R)[1]), "=r"((R)[2]), "=r"((R)[3])   \
                 : "r"(addr))

#define CP_ASYNC16(dst, src)                                                \
    asm volatile("cp.async.cg.shared.global [%0], [%1], 16;"                \
                 :: "r"(dst), "l"(src))
#define CP_COMMIT() asm volatile("cp.async.commit_group;" ::: "memory")
#define CP_WAIT(n)  asm volatile("cp.async.wait_group %0;" :: "n"(n) : "memory")

__device__ __forceinline__ uint32_t smem_u32(const void* p) {
    uint32_t a;
    asm("{ .reg .u64 t; cvta.to.shared.u64 t, %1; cvt.u32.u64 %0, t; }"
        : "=r"(a) : "l"(p));
    return a;
}
__device__ __forceinline__ uint32_t f2tf(float x) {
    uint32_t r;
    asm("cvt.rna.tf32.f32 %0, %1;" : "=r"(r) : "f"(x));
    return r;
}
__device__ __forceinline__ float u2f(uint32_t x) { return __uint_as_float(x); }
__device__ __forceinline__ uint32_t f_as_u(float x) { return __float_as_uint(x); }

// ===========================================================================
// Pre-split: fp32 -> bf16 hi + bf16 lo (hi = rn(x), lo = rn(x - hi))
// ===========================================================================
__global__ __launch_bounds__(256) void split_bf16(const float* __restrict__ in,
                                                  __nv_bfloat16* __restrict__ hi,
                                                  __nv_bfloat16* __restrict__ lo,
                                                  int n4) {
    const int i = blockIdx.x * 256 + threadIdx.x;
    if (i >= n4) return;
    float4 v = ((const float4*)in)[i];
    __nv_bfloat16 h0 = __float2bfloat16_rn(v.x);
    __nv_bfloat16 h1 = __float2bfloat16_rn(v.y);
    __nv_bfloat16 h2 = __float2bfloat16_rn(v.z);
    __nv_bfloat16 h3 = __float2bfloat16_rn(v.w);
    __nv_bfloat16 l0 = __float2bfloat16_rn(v.x - __bfloat162float(h0));
    __nv_bfloat16 l1 = __float2bfloat16_rn(v.y - __bfloat162float(h1));
    __nv_bfloat16 l2 = __float2bfloat16_rn(v.z - __bfloat162float(h2));
    __nv_bfloat16 l3 = __float2bfloat16_rn(v.w - __bfloat162float(h3));
    uint2 ph, pl;
    ph.x = ((uint32_t)__bfloat16_as_ushort(h1) << 16) | __bfloat16_as_ushort(h0);
    ph.y = ((uint32_t)__bfloat16_as_ushort(h3) << 16) | __bfloat16_as_ushort(h2);
    pl.x = ((uint32_t)__bfloat16_as_ushort(l1) << 16) | __bfloat16_as_ushort(l0);
    pl.y = ((uint32_t)__bfloat16_as_ushort(l3) << 16) | __bfloat16_as_ushort(l2);
    ((uint2*)hi)[i] = ph;
    ((uint2*)lo)[i] = pl;
}

// ===========================================================================
// GEMM: C[4096,1024] = A @ W^T via bf16 3-term split mma.sync, cp.async
// double-buffered. Pre-split bf16 hi/lo inputs (no in-loop conversion).
// smem stage (32KB): Ahi 8K | Alo 8K | Bhi 8K | Blo 8K; x2 stages = 64KB.
// Row layout: 128 rows x 64B (32 bf16); 16B chunks XOR-swizzled.
// ===========================================================================
constexpr int NKC = Dm / 32;   // 32 k-chunks
constexpr int GEMM_SMEM = 65536;

__device__ __forceinline__ uint32_t swaddr(uint32_t base, int row, int ch) {
    return base + row * 64 + (((ch) ^ ((row >> 1) & 3)) << 4);
}

__global__ __launch_bounds__(256, 2) void gemm_sp(
        const __nv_bfloat16* __restrict__ Ah, const __nv_bfloat16* __restrict__ Al,
        const __nv_bfloat16* __restrict__ Bh, const __nv_bfloat16* __restrict__ Bl,
        float* __restrict__ C) {
    extern __shared__ char smc[];
    const uint32_t smb = smem_u32(smc);
    const int tid = threadIdx.x;
    const int lane = tid & 31;
    const int wid = tid >> 5;
    const int row0 = blockIdx.y * 128;
    const int col0 = blockIdx.x * 128;
    const int wm = (wid >> 2) * 64;
    const int wn = (wid & 3) * 32;
    const int group = lane >> 2, tig = lane & 3;

    float c[4][4][4];
#pragma unroll
    for (int i = 0; i < 4; ++i)
#pragma unroll
        for (int j = 0; j < 4; ++j)
#pragma unroll
            for (int r = 0; r < 4; ++r) c[i][j][r] = 0.f;

    // cp.async stage issue: 512 chunks per array, 2 per thread per array
    auto issue = [&](int kc, int s) {
        const uint32_t base = smb + s * 32768;
#pragma unroll
        for (int i = 0; i < 2; ++i) {
            const int cidx = tid + i * 256;
            const int row = cidx >> 2, ch = cidx & 3;
            const size_t ga = (size_t)(row0 + row) * Dm + kc * 32 + ch * 8;
            const size_t gb = (size_t)(col0 + row) * Dm + kc * 32 + ch * 8;
            CP_ASYNC16(swaddr(base,         row, ch), Ah + ga);
            CP_ASYNC16(swaddr(base + 8192,  row, ch), Al + ga);
            CP_ASYNC16(swaddr(base + 16384, row, ch), Bh + gb);
            CP_ASYNC16(swaddr(base + 24576, row, ch), Bl + gb);
        }
    };

    issue(0, 0);
    CP_COMMIT();

    for (int kc = 0; kc < NKC; ++kc) {
        if (kc + 1 < NKC) {
            issue(kc + 1, (kc + 1) & 1);
            CP_COMMIT();
            CP_WAIT(1);
        } else {
            CP_WAIT(0);
        }
        __syncthreads();

        const uint32_t sA = smb + (kc & 1) * 32768;
        const uint32_t sB = sA + 16384;
#pragma unroll
        for (int u = 0; u < 2; ++u) {
            uint32_t bh[8], bl8[8];
#pragma unroll
            for (int p = 0; p < 2; ++p) {
                const int nrow = wn + p * 16 + (lane & 15);
                const int chL = u * 2 + (lane >> 4);
                LDSM4(bh + p * 4,  swaddr(sB,        nrow, chL));
                LDSM4(bl8 + p * 4, swaddr(sB + 8192, nrow, chL));
            }
#pragma unroll
            for (int mt = 0; mt < 4; ++mt) {
                const int mrow = wm + mt * 16 + (lane & 15);
                const int chL = u * 2 + (lane >> 4);
                uint32_t ah[4], alr[4];
                LDSM4(ah,  swaddr(sA,        mrow, chL));
                LDSM4(alr, swaddr(sA + 8192, mrow, chL));
#pragma unroll
                for (int j = 0; j < 4; ++j) {
                    const int p = j >> 1, q = j & 1;
                    MMA_BF16(c[mt][j], ah,  bh[p * 4 + q],  bh[p * 4 + q + 2]);
                    MMA_BF16(c[mt][j], ah,  bl8[p * 4 + q], bl8[p * 4 + q + 2]);
                    MMA_BF16(c[mt][j], alr, bh[p * 4 + q],  bh[p * 4 + q + 2]);
                }
            }
        }
        __syncthreads();
    }

    // epilogue
#pragma unroll
    for (int mt = 0; mt < 4; ++mt) {
#pragma unroll
        for (int j = 0; j < 4; ++j) {
            const int r = row0 + wm + mt * 16 + group;
            const int col = col0 + wn + j * 8 + tig * 2;
            float2 v0 = make_float2(c[mt][j][0], c[mt][j][1]);
            float2 v1 = make_float2(c[mt][j][2], c[mt][j][3]);
            *(float2*)(C + (size_t)r * Dm + col)       = v0;
            *(float2*)(C + (size_t)(r + 8) * Dm + col) = v1;
        }
    }
}

// ===========================================================================
// Flash attention, tf32 mma.sync, double-buffered K/V + register prefetch,
// P kept in registers (shfl relayout), one barrier per iteration.
// smem: 2 x (K 64x68 + V 64x72) fp32 = 71680 B.
// ===========================================================================
constexpr int FKS_ST = 68, FVS_ST = 72;
constexpr int TILE_F = 64 * FKS_ST + 64 * FVS_ST;   // 8960 floats per buffer
constexpr int ATT_SMEM = 2 * TILE_F * 4;            // 71680 B

__global__ __launch_bounds__(256) void flash_tf32(const float* __restrict__ Q,
                                                  const float* __restrict__ K,
                                                  const float* __restrict__ V,
                                                  float* __restrict__ O) {
    extern __shared__ float smf[];

    const int tid = threadIdx.x;
    const int lane = tid & 31;
    const int wid = tid >> 5;
    const int group = lane >> 2, tig = lane & 3;
    const int q0 = blockIdx.x * 128;
    const int h = blockIdx.y;
    const int b = blockIdx.z;
    const int wb = wid * 16;

    // Resident Q fragments (scaled + tf32-rna)
    uint32_t qf[8][4];
    {
        const float* Qb = Q + ((size_t)(b * S_ + q0 + wb)) * Dm + h * DK_;
#pragma unroll
        for (int ks = 0; ks < 8; ++ks) {
            const int k0 = ks * 8 + tig;
            qf[ks][0] = f2tf(Qb[(size_t)group * Dm + k0] * ATT_SCALE);
            qf[ks][1] = f2tf(Qb[(size_t)(group + 8) * Dm + k0] * ATT_SCALE);
            qf[ks][2] = f2tf(Qb[(size_t)group * Dm + k0 + 4] * ATT_SCALE);
            qf[ks][3] = f2tf(Qb[(size_t)(group + 8) * Dm + k0 + 4] * ATT_SCALE);
        }
    }

    float of[8][4];
#pragma unroll
    for (int nt = 0; nt < 8; ++nt)
#pragma unroll
        for (int r = 0; r < 4; ++r) of[nt][r] = 0.f;
    float m0 = -1e30f, m1 = -1e30f, l0 = 0.f, l1 = 0.f;

    const float* Kb = K + ((size_t)(b * S_)) * Dm + h * DK_;
    const float* Vb = V + ((size_t)(b * S_)) * Dm + h * DK_;

    // per-thread tile chunk coords (64 rows x 16 float4)
    int trow[4], tc4[4];
#pragma unroll
    for (int i = 0; i < 4; ++i) {
        const int id = tid + i * 256;
        trow[i] = id >> 4;
        tc4[i] = (id & 15) * 4;
    }

    float4 pk[4], pv[4];
    // prologue: tile 0 -> buffer 0
#pragma unroll
    for (int i = 0; i < 4; ++i) {
        pk[i] = *(const float4*)(Kb + (size_t)trow[i] * Dm + tc4[i]);
        pv[i] = *(const float4*)(Vb + (size_t)trow[i] * Dm + tc4[i]);
    }
    {
        float* Ksn = smf;
        float* Vsn = smf + 64 * FKS_ST;
#pragma unroll
        for (int i = 0; i < 4; ++i) {
            float4 ko = make_float4(u2f(f2tf(pk[i].x)), u2f(f2tf(pk[i].y)),
                                    u2f(f2tf(pk[i].z)), u2f(f2tf(pk[i].w)));
            *(float4*)(Ksn + trow[i] * FKS_ST + tc4[i]) = ko;
            float4 vo = make_float4(u2f(f2tf(pv[i].x)), u2f(f2tf(pv[i].y)),
                                    u2f(f2tf(pv[i].z)), u2f(f2tf(pv[i].w)));
            *(float4*)(Vsn + trow[i] * FVS_ST + tc4[i]) = vo;
        }
    }
    __syncthreads();

    const int src0 = (lane & ~3) | (tig >> 1);
    const int src2 = src0 + 2;
    const bool odd = (tig & 1) != 0;

    for (int kt = 0; kt < S_ / 64; ++kt) {
        const int cur = kt & 1;
        float* Ksc = smf + cur * TILE_F;
        float* Vsc = Ksc + 64 * FKS_ST;
        const bool pre = (kt + 1 < S_ / 64);

        if (pre) {
#pragma unroll
            for (int i = 0; i < 4; ++i) {
                pk[i] = *(const float4*)(Kb + (size_t)((kt + 1) * 64 + trow[i]) * Dm + tc4[i]);
                pv[i] = *(const float4*)(Vb + (size_t)((kt + 1) * 64 + trow[i]) * Dm + tc4[i]);
            }
        }

        // S = Q K^T (16 x 64 per warp)
        float sf[8][4];
#pragma unroll
        for (int nt = 0; nt < 8; ++nt)
#pragma unroll
            for (int r = 0; r < 4; ++r) sf[nt][r] = 0.f;
#pragma unroll
        for (int nt = 0; nt < 8; ++nt) {
            const float* krow = Ksc + (nt * 8 + group) * FKS_ST;
#pragma unroll
            for (int ks = 0; ks < 8; ++ks) {
                const uint32_t b0 = f_as_u(krow[ks * 8 + tig]);
                const uint32_t b1 = f_as_u(krow[ks * 8 + tig + 4]);
                MMA_TF32(sf[nt], qf[ks], b0, b1);
            }
        }

        // online softmax on fragments
        float mx0 = -1e30f, mx1 = -1e30f;
#pragma unroll
        for (int nt = 0; nt < 8; ++nt) {
            mx0 = fmaxf(mx0, fmaxf(sf[nt][0], sf[nt][1]));
            mx1 = fmaxf(mx1, fmaxf(sf[nt][2], sf[nt][3]));
        }
        mx0 = fmaxf(mx0, __shfl_xor_sync(0xffffffffu, mx0, 1));
        mx0 = fmaxf(mx0, __shfl_xor_sync(0xffffffffu, mx0, 2));
        mx1 = fmaxf(mx1, __shfl_xor_sync(0xffffffffu, mx1, 1));
        mx1 = fmaxf(mx1, __shfl_xor_sync(0xffffffffu, mx1, 2));
        const float M0 = fmaxf(m0, mx0), M1 = fmaxf(m1, mx1);
        const float al0 = __expf(m0 - M0), al1 = __expf(m1 - M1);
        float s0 = 0.f, s1 = 0.f;
#pragma unroll
        for (int nt = 0; nt < 8; ++nt) {
            sf[nt][0] = __expf(sf[nt][0] - M0);
            sf[nt][1] = __expf(sf[nt][1] - M0);
            sf[nt][2] = __expf(sf[nt][2] - M1);
            sf[nt][3] = __expf(sf[nt][3] - M1);
            s0 += sf[nt][0] + sf[nt][1];
            s1 += sf[nt][2] + sf[nt][3];
        }
        s0 += __shfl_xor_sync(0xffffffffu, s0, 1);
        s0 += __shfl_xor_sync(0xffffffffu, s0, 2);
        s1 += __shfl_xor_sync(0xffffffffu, s1, 1);
        s1 += __shfl_xor_sync(0xffffffffu, s1, 2);
        l0 = l0 * al0 + s0;  m0 = M0;
        l1 = l1 * al1 + s1;  m1 = M1;

        // rescale O, then O += P V (P relayout via shuffles)
#pragma unroll
        for (int nt = 0; nt < 8; ++nt) {
            of[nt][0] *= al0; of[nt][1] *= al0;
            of[nt][2] *= al1; of[nt][3] *= al1;
        }
#pragma unroll
        for (int ks = 0; ks < 8; ++ks) {
            const float a00 = __shfl_sync(0xffffffffu, sf[ks][0], src0);
            const float a01 = __shfl_sync(0xffffffffu, sf[ks][1], src0);
            const float a10 = __shfl_sync(0xffffffffu, sf[ks][2], src0);
            const float a11 = __shfl_sync(0xffffffffu, sf[ks][3], src0);
            const float a20 = __shfl_sync(0xffffffffu, sf[ks][0], src2);
            const float a21 = __shfl_sync(0xffffffffu, sf[ks][1], src2);
            const float a30 = __shfl_sync(0xffffffffu, sf[ks][2], src2);
            const float a31 = __shfl_sync(0xffffffffu, sf[ks][3], src2);
            uint32_t pa[4];
            pa[0] = f2tf(odd ? a01 : a00);
            pa[1] = f2tf(odd ? a11 : a10);
            pa[2] = f2tf(odd ? a21 : a20);
            pa[3] = f2tf(odd ? a31 : a30);
            const float* v0row = Vsc + (ks * 8 + tig) * FVS_ST;
            const float* v1row = Vsc + (ks * 8 + tig + 4) * FVS_ST;
#pragma unroll
            for (int nt = 0; nt < 8; ++nt) {
                const uint32_t b0 = f_as_u(v0row[nt * 8 + group]);
                const uint32_t b1 = f_as_u(v1row[nt * 8 + group]);
                MMA_TF32(of[nt], pa, b0, b1);
            }
        }

        if (pre) {
            float* Ksn = smf + (cur ^ 1) * TILE_F;
            float* Vsn = Ksn + 64 * FKS_ST;
#pragma unroll
            for (int i = 0; i < 4; ++i) {
                float4 ko = make_float4(u2f(f2tf(pk[i].x)), u2f(f2tf(pk[i].y)),
                                        u2f(f2tf(pk[i].z)), u2f(f2tf(pk[i].w)));
                *(float4*)(Ksn + trow[i] * FKS_ST + tc4[i]) = ko;
                float4 vo = make_float4(u2f(f2tf(pv[i].x)), u2f(f2tf(pv[i].y)),
                                        u2f(f2tf(pv[i].z)), u2f(f2tf(pv[i].w)));
                *(float4*)(Vsn + trow[i] * FVS_ST + tc4[i]) = vo;
            }
        }
        __syncthreads();
    }

    // epilogue
    const float i0 = 1.f / l0, i1 = 1.f / l1;
    float* Ob = O + ((size_t)(b * S_ + q0 + wb)) * Dm + h * DK_;
#pragma unroll
    for (int nt = 0; nt < 8; ++nt) {
        float2 v0 = make_float2(of[nt][0] * i0, of[nt][1] * i0);
        float2 v1 = make_float2(of[nt][2] * i1, of[nt][3] * i1);
        *(float2*)(Ob + (size_t)group * Dm + nt * 8 + tig * 2)       = v0;
        *(float2*)(Ob + (size_t)(group + 8) * Dm + nt * 8 + tig * 2) = v1;
    }
}

// ===========================================================================
extern "C" void kernel_launch(void* const* d_in, const int* in_sizes, int n_in,
                              void* d_out, int out_size) {
    const float* x  = (const float*)d_in[0];
    const float* Wq = (const float*)d_in[1];
    const float* Wk = (const float*)d_in[2];
    const float* Wv = (const float*)d_in[3];
    const float* Wo = (const float*)d_in[4];
    float* out = (float*)d_out;

    float *Qp, *Kp, *Vp, *Op;
    __nv_bfloat16 *xh, *xl, *oh, *ol, *wh, *wl;
    cudaGetSymbolAddress((void**)&Qp, g_Q);
    cudaGetSymbolAddress((void**)&Kp, g_K);
    cudaGetSymbolAddress((void**)&Vp, g_V);
    cudaGetSymbolAddress((void**)&Op, g_O);
    cudaGetSymbolAddress((void**)&xh, g_xh);
    cudaGetSymbolAddress((void**)&xl, g_xl);
    cudaGetSymbolAddress((void**)&oh, g_oh);
    cudaGetSymbolAddress((void**)&ol, g_ol);
    cudaGetSymbolAddress((void**)&wh, g_wh);
    cudaGetSymbolAddress((void**)&wl, g_wl);

    cudaFuncSetAttribute(gemm_sp, cudaFuncAttributeMaxDynamicSharedMemorySize,
                         GEMM_SMEM);
    cudaFuncSetAttribute(flash_tf32, cudaFuncAttributeMaxDynamicSharedMemorySize,
                         ATT_SMEM);

    const size_t WN = (size_t)Dm * Dm;  // 1M elements per W
    const int n4x = (Mrows * Dm) / 4;   // 1M float4
    const int n4w = (int)(WN / 4);      // 256K float4

    split_bf16<<<(n4x + 255) / 256, 256>>>(x,  xh, xl, n4x);
    split_bf16<<<(n4w + 255) / 256, 256>>>(Wq, wh + 0 * WN, wl + 0 * WN, n4w);
    split_bf16<<<(n4w + 255) / 256, 256>>>(Wk, wh + 1 * WN, wl + 1 * WN, n4w);
    split_bf16<<<(n4w + 255) / 256, 256>>>(Wv, wh + 2 * WN, wl + 2 * WN, n4w);
    split_bf16<<<(n4w + 255) / 256, 256>>>(Wo, wh + 3 * WN, wl + 3 * WN, n4w);

    const dim3 gProj(Dm / 128, Mrows / 128);      // (8, 32)
    gemm_sp<<<gProj, 256, GEMM_SMEM>>>(xh, xl, wh + 0 * WN, wl + 0 * WN, Qp);
    gemm_sp<<<gProj, 256, GEMM_SMEM>>>(xh, xl, wh + 1 * WN, wl + 1 * WN, Kp);
    gemm_sp<<<gProj, 256, GEMM_SMEM>>>(xh, xl, wh + 2 * WN, wl + 2 * WN, Vp);

    const dim3 gAttn(S_ / 128, H_, B_);           // (16, 16, 2)
    flash_tf32<<<gAttn, 256, ATT_SMEM>>>(Qp, Kp, Vp, Op);

    split_bf16<<<(n4x + 255) / 256, 256>>>(Op, oh, ol, n4x);
    gemm_sp<<<gProj, 256, GEMM_SMEM>>>(oh, ol, wh + 3 * WN, wl + 3 * WN, out);
}

// round 7
// speedup vs baseline: 3.7348x; 1.0497x over previous
#include <cuda_runtime.h>
#include <cuda_bf16.h>
#include <cstdint>

// ===========================================================================
// Problem constants
// ===========================================================================
constexpr int B_   = 2;
constexpr int S_   = 2048;
constexpr int Dm   = 1024;
constexpr int H_   = 16;
constexpr int DK_  = 64;
constexpr int Mrows = B_ * S_;        // 4096
constexpr float ATT_SCALE = 0.125f;   // 1/sqrt(64)

// Scratch (allocation-free: __device__ globals)
__device__ float g_Q[(size_t)Mrows * Dm];
__device__ float g_K[(size_t)Mrows * Dm];
__device__ float g_V[(size_t)Mrows * Dm];
__device__ float g_O[(size_t)Mrows * Dm];
__device__ __nv_bfloat16 g_xh[(size_t)Mrows * Dm];
__device__ __nv_bfloat16 g_xl[(size_t)Mrows * Dm];
__device__ __nv_bfloat16 g_oh[(size_t)Mrows * Dm];
__device__ __nv_bfloat16 g_ol[(size_t)Mrows * Dm];
__device__ __nv_bfloat16 g_wh[(size_t)4 * Dm * Dm];
__device__ __nv_bfloat16 g_wl[(size_t)4 * Dm * Dm];

// ===========================================================================
// mma.sync / ldmatrix / cp.async helpers (legacy tensor path, sm_103 base)
// ===========================================================================
#define MMA_BF16(c, a, b0, b1)                                              \
    asm volatile(                                                           \
        "mma.sync.aligned.m16n8k16.row.col.f32.bf16.bf16.f32 "              \
        "{%0,%1,%2,%3},{%4,%5,%6,%7},{%8,%9},{%0,%1,%2,%3};"                \
        : "+f"((c)[0]), "+f"((c)[1]), "+f"((c)[2]), "+f"((c)[3])            \
        : "r"((a)[0]), "r"((a)[1]), "r"((a)[2]), "r"((a)[3]),               \
          "r"(b0), "r"(b1))

#define MMA_TF32(c, a, b0, b1)                                              \
    asm volatile(                                                           \
        "mma.sync.aligned.m16n8k8.row.col.f32.tf32.tf32.f32 "               \
        "{%0,%1,%2,%3},{%4,%5,%6,%7},{%8,%9},{%0,%1,%2,%3};"                \
        : "+f"((c)[0]), "+f"((c)[1]), "+f"((c)[2]), "+f"((c)[3])            \
        : "r"((a)[0]), "r"((a)[1]), "r"((a)[2]), "r"((a)[3]),               \
          "r"(b0), "r"(b1))

#define LDSM4(R, addr)                                                      \
    asm volatile("ldmatrix.sync.aligned.m8n8.x4.shared.b16 "                \
                 "{%0,%1,%2,%3}, [%4];"                                     \
                 : "=r"((R)[0]), "=r"((R)[1]), "=r"((R)[2]), "=r"((R)[3])   \
                 : "r"(addr))

#define CP_ASYNC16(dst, src)                                                \
    asm volatile("cp.async.cg.shared.global [%0], [%1], 16;"                \
                 :: "r"(dst), "l"(src))
#define CP_COMMIT() asm volatile("cp.async.commit_group;" ::: "memory")
#define CP_WAIT(n)  asm volatile("cp.async.wait_group %0;" :: "n"(n) : "memory")

__device__ __forceinline__ uint32_t smem_u32(const void* p) {
    uint32_t a;
    asm("{ .reg .u64 t; cvta.to.shared.u64 t, %1; cvt.u32.u64 %0, t; }"
        : "=r"(a) : "l"(p));
    return a;
}
__device__ __forceinline__ uint32_t f2tf(float x) {
    uint32_t r;
    asm("cvt.rna.tf32.f32 %0, %1;" : "=r"(r) : "f"(x));
    return r;
}
__device__ __forceinline__ float u2f(uint32_t x) { return __uint_as_float(x); }
__device__ __forceinline__ uint32_t f_as_u(float x) { return __float_as_uint(x); }

// ===========================================================================
// Pre-split: fp32 -> bf16 hi + bf16 lo (hi = rn(x), lo = rn(x - hi))
// ===========================================================================
__global__ __launch_bounds__(256) void split_bf16(const float* __restrict__ in,
                                                  __nv_bfloat16* __restrict__ hi,
                                                  __nv_bfloat16* __restrict__ lo,
                                                  int n4) {
    const int i = blockIdx.x * 256 + threadIdx.x;
    if (i >= n4) return;
    float4 v = ((const float4*)in)[i];
    __nv_bfloat16 h0 = __float2bfloat16_rn(v.x);
    __nv_bfloat16 h1 = __float2bfloat16_rn(v.y);
    __nv_bfloat16 h2 = __float2bfloat16_rn(v.z);
    __nv_bfloat16 h3 = __float2bfloat16_rn(v.w);
    __nv_bfloat16 l0 = __float2bfloat16_rn(v.x - __bfloat162float(h0));
    __nv_bfloat16 l1 = __float2bfloat16_rn(v.y - __bfloat162float(h1));
    __nv_bfloat16 l2 = __float2bfloat16_rn(v.z - __bfloat162float(h2));
    __nv_bfloat16 l3 = __float2bfloat16_rn(v.w - __bfloat162float(h3));
    uint2 ph, pl;
    ph.x = ((uint32_t)__bfloat16_as_ushort(h1) << 16) | __bfloat16_as_ushort(h0);
    ph.y = ((uint32_t)__bfloat16_as_ushort(h3) << 16) | __bfloat16_as_ushort(h2);
    pl.x = ((uint32_t)__bfloat16_as_ushort(l1) << 16) | __bfloat16_as_ushort(l0);
    pl.y = ((uint32_t)__bfloat16_as_ushort(l3) << 16) | __bfloat16_as_ushort(l2);
    ((uint2*)hi)[i] = ph;
    ((uint2*)lo)[i] = pl;
}

// ===========================================================================
// GEMM: C[4096,1024] = A @ W^T via bf16 3-term split mma.sync, cp.async
// double-buffered (unchanged from R6 passing version).
// ===========================================================================
constexpr int NKC = Dm / 32;   // 32 k-chunks
constexpr int GEMM_SMEM = 65536;

__device__ __forceinline__ uint32_t swaddr(uint32_t base, int row, int ch) {
    return base + row * 64 + (((ch) ^ ((row >> 1) & 3)) << 4);
}

__global__ __launch_bounds__(256, 2) void gemm_sp(
        const __nv_bfloat16* __restrict__ Ah, const __nv_bfloat16* __restrict__ Al,
        const __nv_bfloat16* __restrict__ Bh, const __nv_bfloat16* __restrict__ Bl,
        float* __restrict__ C) {
    extern __shared__ char smc[];
    const uint32_t smb = smem_u32(smc);
    const int tid = threadIdx.x;
    const int lane = tid & 31;
    const int wid = tid >> 5;
    const int row0 = blockIdx.y * 128;
    const int col0 = blockIdx.x * 128;
    const int wm = (wid >> 2) * 64;
    const int wn = (wid & 3) * 32;
    const int group = lane >> 2, tig = lane & 3;

    float c[4][4][4];
#pragma unroll
    for (int i = 0; i < 4; ++i)
#pragma unroll
        for (int j = 0; j < 4; ++j)
#pragma unroll
            for (int r = 0; r < 4; ++r) c[i][j][r] = 0.f;

    auto issue = [&](int kc, int s) {
        const uint32_t base = smb + s * 32768;
#pragma unroll
        for (int i = 0; i < 2; ++i) {
            const int cidx = tid + i * 256;
            const int row = cidx >> 2, ch = cidx & 3;
            const size_t ga = (size_t)(row0 + row) * Dm + kc * 32 + ch * 8;
            const size_t gb = (size_t)(col0 + row) * Dm + kc * 32 + ch * 8;
            CP_ASYNC16(swaddr(base,         row, ch), Ah + ga);
            CP_ASYNC16(swaddr(base + 8192,  row, ch), Al + ga);
            CP_ASYNC16(swaddr(base + 16384, row, ch), Bh + gb);
            CP_ASYNC16(swaddr(base + 24576, row, ch), Bl + gb);
        }
    };

    issue(0, 0);
    CP_COMMIT();

    for (int kc = 0; kc < NKC; ++kc) {
        if (kc + 1 < NKC) {
            issue(kc + 1, (kc + 1) & 1);
            CP_COMMIT();
            CP_WAIT(1);
        } else {
            CP_WAIT(0);
        }
        __syncthreads();

        const uint32_t sA = smb + (kc & 1) * 32768;
        const uint32_t sB = sA + 16384;
#pragma unroll
        for (int u = 0; u < 2; ++u) {
            uint32_t bh[8], bl8[8];
#pragma unroll
            for (int p = 0; p < 2; ++p) {
                const int nrow = wn + p * 16 + (lane & 15);
                const int chL = u * 2 + (lane >> 4);
                LDSM4(bh + p * 4,  swaddr(sB,        nrow, chL));
                LDSM4(bl8 + p * 4, swaddr(sB + 8192, nrow, chL));
            }
#pragma unroll
            for (int mt = 0; mt < 4; ++mt) {
                const int mrow = wm + mt * 16 + (lane & 15);
                const int chL = u * 2 + (lane >> 4);
                uint32_t ah[4], alr[4];
                LDSM4(ah,  swaddr(sA,        mrow, chL));
                LDSM4(alr, swaddr(sA + 8192, mrow, chL));
#pragma unroll
                for (int j = 0; j < 4; ++j) {
                    const int p = j >> 1, q = j & 1;
                    MMA_BF16(c[mt][j], ah,  bh[p * 4 + q],  bh[p * 4 + q + 2]);
                    MMA_BF16(c[mt][j], ah,  bl8[p * 4 + q], bl8[p * 4 + q + 2]);
                    MMA_BF16(c[mt][j], alr, bh[p * 4 + q],  bh[p * 4 + q + 2]);
                }
            }
        }
        __syncthreads();
    }

#pragma unroll
    for (int mt = 0; mt < 4; ++mt) {
#pragma unroll
        for (int j = 0; j < 4; ++j) {
            const int r = row0 + wm + mt * 16 + group;
            const int col = col0 + wn + j * 8 + tig * 2;
            float2 v0 = make_float2(c[mt][j][0], c[mt][j][1]);
            float2 v1 = make_float2(c[mt][j][2], c[mt][j][3]);
            *(float2*)(C + (size_t)r * Dm + col)       = v0;
            *(float2*)(C + (size_t)(r + 8) * Dm + col) = v1;
        }
    }
}

// ===========================================================================
// Flash attention, tf32 mma.sync.
// NEW: K/V loaded via cp.async double-buffering (raw fp32; HW tf32
// truncation on the B operand). No prefetch registers, no cvt/STS loader.
// __launch_bounds__(256,2) -> 2 CTAs/SM (smem 2x70KB = 140KB < 228KB).
// Strides 68/72 floats are 16B multiples (cp.async-compatible) and give
// conflict-free reads (K banks 4g+8ks+t; V banks 8t+g).
// ===========================================================================
constexpr int FKS_ST = 68, FVS_ST = 72;
constexpr int TILE_F = 64 * FKS_ST + 64 * FVS_ST;   // 8960 floats per buffer
constexpr int ATT_SMEM = 2 * TILE_F * 4;            // 71680 B
constexpr int NT_ = S_ / 64;                        // 32 tiles

__global__ __launch_bounds__(256, 2) void flash_tf32(const float* __restrict__ Q,
                                                     const float* __restrict__ K,
                                                     const float* __restrict__ V,
                                                     float* __restrict__ O) {
    extern __shared__ float smf[];
    const uint32_t smb = smem_u32(smf);

    const int tid = threadIdx.x;
    const int lane = tid & 31;
    const int wid = tid >> 5;
    const int group = lane >> 2, tig = lane & 3;
    const int q0 = blockIdx.x * 128;
    const int h = blockIdx.y;
    const int b = blockIdx.z;
    const int wb = wid * 16;

    const float* Kb = K + ((size_t)(b * S_)) * Dm + h * DK_;
    const float* Vb = V + ((size_t)(b * S_)) * Dm + h * DK_;

    // cp.async stage: 64 rows x 16 chunks for K and V each (2048 chunks,
    // 8 per thread)
    auto issue = [&](int kt, int s) {
        const uint32_t kbase = smb + s * (TILE_F * 4);
        const uint32_t vbase = kbase + 64 * FKS_ST * 4;
#pragma unroll
        for (int i = 0; i < 4; ++i) {
            const int id = tid + i * 256;          // 0..1023
            const int r = id >> 4, ch = id & 15;
            const size_t g = (size_t)(kt * 64 + r) * Dm + ch * 4;
            CP_ASYNC16(kbase + r * (FKS_ST * 4) + ch * 16, Kb + g);
            CP_ASYNC16(vbase + r * (FVS_ST * 4) + ch * 16, Vb + g);
        }
    };

    issue(0, 0);
    CP_COMMIT();

    // Resident Q fragments (scaled + tf32-rna) — loads overlap stage 0 copy
    uint32_t qf[8][4];
    {
        const float* Qb = Q + ((size_t)(b * S_ + q0 + wb)) * Dm + h * DK_;
#pragma unroll
        for (int ks = 0; ks < 8; ++ks) {
            const int k0 = ks * 8 + tig;
            qf[ks][0] = f2tf(Qb[(size_t)group * Dm + k0] * ATT_SCALE);
            qf[ks][1] = f2tf(Qb[(size_t)(group + 8) * Dm + k0] * ATT_SCALE);
            qf[ks][2] = f2tf(Qb[(size_t)group * Dm + k0 + 4] * ATT_SCALE);
            qf[ks][3] = f2tf(Qb[(size_t)(group + 8) * Dm + k0 + 4] * ATT_SCALE);
        }
    }

    float of[8][4];
#pragma unroll
    for (int nt = 0; nt < 8; ++nt)
#pragma unroll
        for (int r = 0; r < 4; ++r) of[nt][r] = 0.f;
    float m0 = -1e30f, m1 = -1e30f, l0 = 0.f, l1 = 0.f;

    const int src0 = (lane & ~3) | (tig >> 1);
    const int src2 = src0 + 2;
    const bool odd = (tig & 1) != 0;

    for (int kt = 0; kt < NT_; ++kt) {
        if (kt + 1 < NT_) {
            issue(kt + 1, (kt + 1) & 1);
            CP_COMMIT();
            CP_WAIT(1);
        } else {
            CP_WAIT(0);
        }
        __syncthreads();

        const float* Ksc = smf + (kt & 1) * TILE_F;
        const float* Vsc = Ksc + 64 * FKS_ST;

        // S = Q K^T (16 x 64 per warp); K raw fp32 -> HW tf32 truncation
        float sf[8][4];
#pragma unroll
        for (int nt = 0; nt < 8; ++nt)
#pragma unroll
            for (int r = 0; r < 4; ++r) sf[nt][r] = 0.f;
#pragma unroll
        for (int nt = 0; nt < 8; ++nt) {
            const float* krow = Ksc + (nt * 8 + group) * FKS_ST;
#pragma unroll
            for (int ks = 0; ks < 8; ++ks) {
                const uint32_t b0 = f_as_u(krow[ks * 8 + tig]);
                const uint32_t b1 = f_as_u(krow[ks * 8 + tig + 4]);
                MMA_TF32(sf[nt], qf[ks], b0, b1);
            }
        }

        // online softmax on fragments
        float mx0 = -1e30f, mx1 = -1e30f;
#pragma unroll
        for (int nt = 0; nt < 8; ++nt) {
            mx0 = fmaxf(mx0, fmaxf(sf[nt][0], sf[nt][1]));
            mx1 = fmaxf(mx1, fmaxf(sf[nt][2], sf[nt][3]));
        }
        mx0 = fmaxf(mx0, __shfl_xor_sync(0xffffffffu, mx0, 1));
        mx0 = fmaxf(mx0, __shfl_xor_sync(0xffffffffu, mx0, 2));
        mx1 = fmaxf(mx1, __shfl_xor_sync(0xffffffffu, mx1, 1));
        mx1 = fmaxf(mx1, __shfl_xor_sync(0xffffffffu, mx1, 2));
        const float M0 = fmaxf(m0, mx0), M1 = fmaxf(m1, mx1);
        const float al0 = __expf(m0 - M0), al1 = __expf(m1 - M1);
        float s0 = 0.f, s1 = 0.f;
#pragma unroll
        for (int nt = 0; nt < 8; ++nt) {
            sf[nt][0] = __expf(sf[nt][0] - M0);
            sf[nt][1] = __expf(sf[nt][1] - M0);
            sf[nt][2] = __expf(sf[nt][2] - M1);
            sf[nt][3] = __expf(sf[nt][3] - M1);
            s0 += sf[nt][0] + sf[nt][1];
            s1 += sf[nt][2] + sf[nt][3];
        }
        s0 += __shfl_xor_sync(0xffffffffu, s0, 1);
        s0 += __shfl_xor_sync(0xffffffffu, s0, 2);
        s1 += __shfl_xor_sync(0xffffffffu, s1, 1);
        s1 += __shfl_xor_sync(0xffffffffu, s1, 2);
        l0 = l0 * al0 + s0;  m0 = M0;
        l1 = l1 * al1 + s1;  m1 = M1;

        // rescale O, then O += P V (P relayout via shuffles; V raw fp32)
#pragma unroll
        for (int nt = 0; nt < 8; ++nt) {
            of[nt][0] *= al0; of[nt][1] *= al0;
            of[nt][2] *= al1; of[nt][3] *= al1;
        }
#pragma unroll
        for (int ks = 0; ks < 8; ++ks) {
            const float a00 = __shfl_sync(0xffffffffu, sf[ks][0], src0);
            const float a01 = __shfl_sync(0xffffffffu, sf[ks][1], src0);
            const float a10 = __shfl_sync(0xffffffffu, sf[ks][2], src0);
            const float a11 = __shfl_sync(0xffffffffu, sf[ks][3], src0);
            const float a20 = __shfl_sync(0xffffffffu, sf[ks][0], src2);
            const float a21 = __shfl_sync(0xffffffffu, sf[ks][1], src2);
            const float a30 = __shfl_sync(0xffffffffu, sf[ks][2], src2);
            const float a31 = __shfl_sync(0xffffffffu, sf[ks][3], src2);
            uint32_t pa[4];
            pa[0] = f2tf(odd ? a01 : a00);
            pa[1] = f2tf(odd ? a11 : a10);
            pa[2] = f2tf(odd ? a21 : a20);
            pa[3] = f2tf(odd ? a31 : a30);
            const float* v0row = Vsc + (ks * 8 + tig) * FVS_ST;
            const float* v1row = Vsc + (ks * 8 + tig + 4) * FVS_ST;
#pragma unroll
            for (int nt = 0; nt < 8; ++nt) {
                const uint32_t b0 = f_as_u(v0row[nt * 8 + group]);
                const uint32_t b1 = f_as_u(v1row[nt * 8 + group]);
                MMA_TF32(of[nt], pa, b0, b1);
            }
        }
        __syncthreads();
    }

    // epilogue
    const float i0 = 1.f / l0, i1 = 1.f / l1;
    float* Ob = O + ((size_t)(b * S_ + q0 + wb)) * Dm + h * DK_;
#pragma unroll
    for (int nt = 0; nt < 8; ++nt) {
        float2 v0 = make_float2(of[nt][0] * i0, of[nt][1] * i0);
        float2 v1 = make_float2(of[nt][2] * i1, of[nt][3] * i1);
        *(float2*)(Ob + (size_t)group * Dm + nt * 8 + tig * 2)       = v0;
        *(float2*)(Ob + (size_t)(group + 8) * Dm + nt * 8 + tig * 2) = v1;
    }
}

// ===========================================================================
extern "C" void kernel_launch(void* const* d_in, const int* in_sizes, int n_in,
                              void* d_out, int out_size) {
    const float* x  = (const float*)d_in[0];
    const float* Wq = (const float*)d_in[1];
    const float* Wk = (const float*)d_in[2];
    const float* Wv = (const float*)d_in[3];
    const float* Wo = (const float*)d_in[4];
    float* out = (float*)d_out;

    float *Qp, *Kp, *Vp, *Op;
    __nv_bfloat16 *xh, *xl, *oh, *ol, *wh, *wl;
    cudaGetSymbolAddress((void**)&Qp, g_Q);
    cudaGetSymbolAddress((void**)&Kp, g_K);
    cudaGetSymbolAddress((void**)&Vp, g_V);
    cudaGetSymbolAddress((void**)&Op, g_O);
    cudaGetSymbolAddress((void**)&xh, g_xh);
    cudaGetSymbolAddress((void**)&xl, g_xl);
    cudaGetSymbolAddress((void**)&oh, g_oh);
    cudaGetSymbolAddress((void**)&ol, g_ol);
    cudaGetSymbolAddress((void**)&wh, g_wh);
    cudaGetSymbolAddress((void**)&wl, g_wl);

    cudaFuncSetAttribute(gemm_sp, cudaFuncAttributeMaxDynamicSharedMemorySize,
                         GEMM_SMEM);
    cudaFuncSetAttribute(flash_tf32, cudaFuncAttributeMaxDynamicSharedMemorySize,
                         ATT_SMEM);

    const size_t WN = (size_t)Dm * Dm;  // 1M elements per W
    const int n4x = (Mrows * Dm) / 4;   // 1M float4
    const int n4w = (int)(WN / 4);      // 256K float4

    split_bf16<<<(n4x + 255) / 256, 256>>>(x,  xh, xl, n4x);
    split_bf16<<<(n4w + 255) / 256, 256>>>(Wq, wh + 0 * WN, wl + 0 * WN, n4w);
    split_bf16<<<(n4w + 255) / 256, 256>>>(Wk, wh + 1 * WN, wl + 1 * WN, n4w);
    split_bf16<<<(n4w + 255) / 256, 256>>>(Wv, wh + 2 * WN, wl + 2 * WN, n4w);
    split_bf16<<<(n4w + 255) / 256, 256>>>(Wo, wh + 3 * WN, wl + 3 * WN, n4w);

    const dim3 gProj(Dm / 128, Mrows / 128);      // (8, 32)
    gemm_sp<<<gProj, 256, GEMM_SMEM>>>(xh, xl, wh + 0 * WN, wl + 0 * WN, Qp);
    gemm_sp<<<gProj, 256, GEMM_SMEM>>>(xh, xl, wh + 1 * WN, wl + 1 * WN, Kp);
    gemm_sp<<<gProj, 256, GEMM_SMEM>>>(xh, xl, wh + 2 * WN, wl + 2 * WN, Vp);

    const dim3 gAttn(S_ / 128, H_, B_);           // (16, 16, 2)
    flash_tf32<<<gAttn, 256, ATT_SMEM>>>(Qp, Kp, Vp, Op);

    split_bf16<<<(n4x + 255) / 256, 256>>>(Op, oh, ol, n4x);
    gemm_sp<<<gProj, 256, GEMM_SMEM>>>(oh, ol, wh + 3 * WN, wl + 3 * WN, out);
}

// round 8
// speedup vs baseline: 3.7671x; 1.0086x over previous
#include <cuda_runtime.h>
#include <cuda_bf16.h>
#include <cstdint>

// ===========================================================================
// Problem constants
// ===========================================================================
constexpr int B_   = 2;
constexpr int S_   = 2048;
constexpr int Dm   = 1024;
constexpr int H_   = 16;
constexpr int DK_  = 64;
constexpr int Mrows = B_ * S_;        // 4096
constexpr float ATT_SCALE = 0.125f;   // 1/sqrt(64)

// Scratch (allocation-free: __device__ globals)
__device__ float g_Q[(size_t)Mrows * Dm];
__device__ float g_K[(size_t)Mrows * Dm];
__device__ float g_V[(size_t)Mrows * Dm];
__device__ __nv_bfloat16 g_xh[(size_t)Mrows * Dm];
__device__ __nv_bfloat16 g_xl[(size_t)Mrows * Dm];
__device__ __nv_bfloat16 g_oh[(size_t)Mrows * Dm];
__device__ __nv_bfloat16 g_ol[(size_t)Mrows * Dm];
__device__ __nv_bfloat16 g_wh[(size_t)4 * Dm * Dm];
__device__ __nv_bfloat16 g_wl[(size_t)4 * Dm * Dm];

// ===========================================================================
// mma.sync / ldmatrix / cp.async helpers (legacy tensor path, sm_103 base)
// ===========================================================================
#define MMA_BF16(c, a, b0, b1)                                              \
    asm volatile(                                                           \
        "mma.sync.aligned.m16n8k16.row.col.f32.bf16.bf16.f32 "              \
        "{%0,%1,%2,%3},{%4,%5,%6,%7},{%8,%9},{%0,%1,%2,%3};"                \
        : "+f"((c)[0]), "+f"((c)[1]), "+f"((c)[2]), "+f"((c)[3])            \
        : "r"((a)[0]), "r"((a)[1]), "r"((a)[2]), "r"((a)[3]),               \
          "r"(b0), "r"(b1))

#define MMA_TF32(c, a, b0, b1)                                              \
    asm volatile(                                                           \
        "mma.sync.aligned.m16n8k8.row.col.f32.tf32.tf32.f32 "               \
        "{%0,%1,%2,%3},{%4,%5,%6,%7},{%8,%9},{%0,%1,%2,%3};"                \
        : "+f"((c)[0]), "+f"((c)[1]), "+f"((c)[2]), "+f"((c)[3])            \
        : "r"((a)[0]), "r"((a)[1]), "r"((a)[2]), "r"((a)[3]),               \
          "r"(b0), "r"(b1))

#define LDSM4(R, addr)                                                      \
    asm volatile("ldmatrix.sync.aligned.m8n8.x4.shared.b16 "                \
                 "{%0,%1,%2,%3}, [%4];"                                     \
                 : "=r"((R)[0]), "=r"((R)[1]), "=r"((R)[2]), "=r"((R)[3])   \
                 : "r"(addr))

#define CP_ASYNC16(dst, src)                                                \
    asm volatile("cp.async.cg.shared.global [%0], [%1], 16;"                \
                 :: "r"(dst), "l"(src))
#define CP_COMMIT() asm volatile("cp.async.commit_group;" ::: "memory")
#define CP_WAIT(n)  asm volatile("cp.async.wait_group %0;" :: "n"(n) : "memory")

__device__ __forceinline__ uint32_t smem_u32(const void* p) {
    uint32_t a;
    asm("{ .reg .u64 t; cvta.to.shared.u64 t, %1; cvt.u32.u64 %0, t; }"
        : "=r"(a) : "l"(p));
    return a;
}
__device__ __forceinline__ uint32_t f2tf(float x) {
    uint32_t r;
    asm("cvt.rna.tf32.f32 %0, %1;" : "=r"(r) : "f"(x));
    return r;
}
__device__ __forceinline__ float u2f(uint32_t x) { return __uint_as_float(x); }
__device__ __forceinline__ uint32_t f_as_u(float x) { return __float_as_uint(x); }

__device__ __forceinline__ uint32_t pack_hi2(float x, float y) {
    __nv_bfloat16 hx = __float2bfloat16_rn(x);
    __nv_bfloat16 hy = __float2bfloat16_rn(y);
    return ((uint32_t)__bfloat16_as_ushort(hy) << 16) | __bfloat16_as_ushort(hx);
}
__device__ __forceinline__ uint32_t pack_lo2(float x, float y) {
    __nv_bfloat16 hx = __float2bfloat16_rn(x);
    __nv_bfloat16 hy = __float2bfloat16_rn(y);
    __nv_bfloat16 lx = __float2bfloat16_rn(x - __bfloat162float(hx));
    __nv_bfloat16 ly = __float2bfloat16_rn(y - __bfloat162float(hy));
    return ((uint32_t)__bfloat16_as_ushort(ly) << 16) | __bfloat16_as_ushort(lx);
}

// ===========================================================================
// Pre-split: fp32 -> bf16 hi + bf16 lo
// ===========================================================================
__global__ __launch_bounds__(256) void split_bf16(const float* __restrict__ in,
                                                  __nv_bfloat16* __restrict__ hi,
                                                  __nv_bfloat16* __restrict__ lo,
                                                  int n4) {
    const int i = blockIdx.x * 256 + threadIdx.x;
    if (i >= n4) return;
    float4 v = ((const float4*)in)[i];
    uint2 ph, pl;
    ph.x = pack_hi2(v.x, v.y);  ph.y = pack_hi2(v.z, v.w);
    pl.x = pack_lo2(v.x, v.y);  pl.y = pack_lo2(v.z, v.w);
    ((uint2*)hi)[i] = ph;
    ((uint2*)lo)[i] = pl;
}

// All 4 weight matrices in one launch (outputs contiguous in g_wh/g_wl).
__global__ __launch_bounds__(256) void split_w4(const float* __restrict__ w0,
                                                const float* __restrict__ w1,
                                                const float* __restrict__ w2,
                                                const float* __restrict__ w3,
                                                __nv_bfloat16* __restrict__ hi,
                                                __nv_bfloat16* __restrict__ lo,
                                                int n4each) {
    const int i = blockIdx.x * 256 + threadIdx.x;
    if (i >= 4 * n4each) return;
    const int w = i / n4each, j = i - w * n4each;
    const float* src = (w == 0) ? w0 : (w == 1) ? w1 : (w == 2) ? w2 : w3;
    float4 v = ((const float4*)src)[j];
    uint2 ph, pl;
    ph.x = pack_hi2(v.x, v.y);  ph.y = pack_hi2(v.z, v.w);
    pl.x = pack_lo2(v.x, v.y);  pl.y = pack_lo2(v.z, v.w);
    ((uint2*)hi)[i] = ph;
    ((uint2*)lo)[i] = pl;
}

// ===========================================================================
// GEMM core: 128x128 tile, bf16 3-term split, 3-stage cp.async pipeline.
// smem stage (32KB): Ahi 8K | Alo 8K | Bhi 8K | Blo 8K; x3 stages = 96KB.
// ===========================================================================
constexpr int NKC = Dm / 32;          // 32 k-chunks
constexpr int GEMM_SMEM = 3 * 32768;  // 98304

__device__ __forceinline__ uint32_t swaddr(uint32_t base, int row, int ch) {
    return base + row * 64 + (((ch) ^ ((row >> 1) & 3)) << 4);
}

__device__ __forceinline__ void gemm_core(
        const __nv_bfloat16* __restrict__ Ah, const __nv_bfloat16* __restrict__ Al,
        const __nv_bfloat16* __restrict__ Bh, const __nv_bfloat16* __restrict__ Bl,
        float* __restrict__ C, int row0, int col0, uint32_t smb) {
    const int tid = threadIdx.x;
    const int lane = tid & 31;
    const int wid = tid >> 5;
    const int wm = (wid >> 2) * 64;
    const int wn = (wid & 3) * 32;
    const int group = lane >> 2, tig = lane & 3;

    float c[4][4][4];
#pragma unroll
    for (int i = 0; i < 4; ++i)
#pragma unroll
        for (int j = 0; j < 4; ++j)
#pragma unroll
            for (int r = 0; r < 4; ++r) c[i][j][r] = 0.f;

    auto issue = [&](int kc, int s) {
        const uint32_t base = smb + s * 32768;
#pragma unroll
        for (int i = 0; i < 2; ++i) {
            const int cidx = tid + i * 256;
            const int row = cidx >> 2, ch = cidx & 3;
            const size_t ga = (size_t)(row0 + row) * Dm + kc * 32 + ch * 8;
            const size_t gb = (size_t)(col0 + row) * Dm + kc * 32 + ch * 8;
            CP_ASYNC16(swaddr(base,         row, ch), Ah + ga);
            CP_ASYNC16(swaddr(base + 8192,  row, ch), Al + ga);
            CP_ASYNC16(swaddr(base + 16384, row, ch), Bh + gb);
            CP_ASYNC16(swaddr(base + 24576, row, ch), Bl + gb);
        }
    };

    issue(0, 0); CP_COMMIT();
    issue(1, 1); CP_COMMIT();

    int stage = 0;
    for (int kc = 0; kc < NKC; ++kc) {
        if (kc + 2 < NKC) {
            issue(kc + 2, (stage + 2) % 3);
            CP_COMMIT();
            CP_WAIT(2);
        } else if (kc + 1 < NKC) {
            CP_WAIT(1);
        } else {
            CP_WAIT(0);
        }
        __syncthreads();

        const uint32_t sA = smb + stage * 32768;
        const uint32_t sB = sA + 16384;
#pragma unroll
        for (int u = 0; u < 2; ++u) {
            uint32_t bh[8], bl8[8];
#pragma unroll
            for (int p = 0; p < 2; ++p) {
                const int nrow = wn + p * 16 + (lane & 15);
                const int chL = u * 2 + (lane >> 4);
                LDSM4(bh + p * 4,  swaddr(sB,        nrow, chL));
                LDSM4(bl8 + p * 4, swaddr(sB + 8192, nrow, chL));
            }
#pragma unroll
            for (int mt = 0; mt < 4; ++mt) {
                const int mrow = wm + mt * 16 + (lane & 15);
                const int chL = u * 2 + (lane >> 4);
                uint32_t ah[4], alr[4];
                LDSM4(ah,  swaddr(sA,        mrow, chL));
                LDSM4(alr, swaddr(sA + 8192, mrow, chL));
#pragma unroll
                for (int j = 0; j < 4; ++j) {
                    const int p = j >> 1, q = j & 1;
                    MMA_BF16(c[mt][j], ah,  bh[p * 4 + q],  bh[p * 4 + q + 2]);
                    MMA_BF16(c[mt][j], ah,  bl8[p * 4 + q], bl8[p * 4 + q + 2]);
                    MMA_BF16(c[mt][j], alr, bh[p * 4 + q],  bh[p * 4 + q + 2]);
                }
            }
        }
        __syncthreads();
        stage = (stage + 1) % 3;
    }

#pragma unroll
    for (int mt = 0; mt < 4; ++mt) {
#pragma unroll
        for (int j = 0; j < 4; ++j) {
            const int r = row0 + wm + mt * 16 + group;
            const int col = col0 + wn + j * 8 + tig * 2;
            float2 v0 = make_float2(c[mt][j][0], c[mt][j][1]);
            float2 v1 = make_float2(c[mt][j][2], c[mt][j][3]);
            *(float2*)(C + (size_t)r * Dm + col)       = v0;
            *(float2*)(C + (size_t)(r + 8) * Dm + col) = v1;
        }
    }
}

// Fused Q/K/V projection: blockIdx.z selects weight slice + destination.
__global__ __launch_bounds__(256, 2) void gemm_qkv(
        const __nv_bfloat16* __restrict__ xh, const __nv_bfloat16* __restrict__ xl,
        const __nv_bfloat16* __restrict__ Wh, const __nv_bfloat16* __restrict__ Wl,
        float* __restrict__ Q, float* __restrict__ K, float* __restrict__ V) {
    extern __shared__ char smc[];
    const int z = blockIdx.z;
    const size_t WN = (size_t)Dm * Dm;
    float* C = (z == 0) ? Q : (z == 1) ? K : V;
    gemm_core(xh, xl, Wh + z * WN, Wl + z * WN, C,
              blockIdx.y * 128, blockIdx.x * 128, smem_u32(smc));
}

__global__ __launch_bounds__(256, 2) void gemm_sp(
        const __nv_bfloat16* __restrict__ Ah, const __nv_bfloat16* __restrict__ Al,
        const __nv_bfloat16* __restrict__ Bh, const __nv_bfloat16* __restrict__ Bl,
        float* __restrict__ C) {
    extern __shared__ char smc[];
    gemm_core(Ah, Al, Bh, Bl, C, blockIdx.y * 128, blockIdx.x * 128,
              smem_u32(smc));
}

// ===========================================================================
// Flash attention, tf32 mma.sync, cp.async double-buffered K/V.
// Epilogue writes O directly as bf16 hi/lo (identical split to split_bf16),
// removing the fp32 O round-trip + split launch.
// ===========================================================================
constexpr int FKS_ST = 68, FVS_ST = 72;
constexpr int TILE_F = 64 * FKS_ST + 64 * FVS_ST;   // 8960 floats per buffer
constexpr int ATT_SMEM = 2 * TILE_F * 4;            // 71680 B
constexpr int NT_ = S_ / 64;                        // 32 tiles

__global__ __launch_bounds__(256, 2) void flash_tf32(
        const float* __restrict__ Q, const float* __restrict__ K,
        const float* __restrict__ V,
        __nv_bfloat16* __restrict__ OH, __nv_bfloat16* __restrict__ OL) {
    extern __shared__ float smf[];
    const uint32_t smb = smem_u32(smf);

    const int tid = threadIdx.x;
    const int lane = tid & 31;
    const int wid = tid >> 5;
    const int group = lane >> 2, tig = lane & 3;
    const int q0 = blockIdx.x * 128;
    const int h = blockIdx.y;
    const int b = blockIdx.z;
    const int wb = wid * 16;

    const float* Kb = K + ((size_t)(b * S_)) * Dm + h * DK_;
    const float* Vb = V + ((size_t)(b * S_)) * Dm + h * DK_;

    auto issue = [&](int kt, int s) {
        const uint32_t kbase = smb + s * (TILE_F * 4);
        const uint32_t vbase = kbase + 64 * FKS_ST * 4;
#pragma unroll
        for (int i = 0; i < 4; ++i) {
            const int id = tid + i * 256;
            const int r = id >> 4, ch = id & 15;
            const size_t g = (size_t)(kt * 64 + r) * Dm + ch * 4;
            CP_ASYNC16(kbase + r * (FKS_ST * 4) + ch * 16, Kb + g);
            CP_ASYNC16(vbase + r * (FVS_ST * 4) + ch * 16, Vb + g);
        }
    };

    issue(0, 0);
    CP_COMMIT();

    uint32_t qf[8][4];
    {
        const float* Qb = Q + ((size_t)(b * S_ + q0 + wb)) * Dm + h * DK_;
#pragma unroll
        for (int ks = 0; ks < 8; ++ks) {
            const int k0 = ks * 8 + tig;
            qf[ks][0] = f2tf(Qb[(size_t)group * Dm + k0] * ATT_SCALE);
            qf[ks][1] = f2tf(Qb[(size_t)(group + 8) * Dm + k0] * ATT_SCALE);
            qf[ks][2] = f2tf(Qb[(size_t)group * Dm + k0 + 4] * ATT_SCALE);
            qf[ks][3] = f2tf(Qb[(size_t)(group + 8) * Dm + k0 + 4] * ATT_SCALE);
        }
    }

    float of[8][4];
#pragma unroll
    for (int nt = 0; nt < 8; ++nt)
#pragma unroll
        for (int r = 0; r < 4; ++r) of[nt][r] = 0.f;
    float m0 = -1e30f, m1 = -1e30f, l0 = 0.f, l1 = 0.f;

    const int src0 = (lane & ~3) | (tig >> 1);
    const int src2 = src0 + 2;
    const bool odd = (tig & 1) != 0;

    for (int kt = 0; kt < NT_; ++kt) {
        if (kt + 1 < NT_) {
            issue(kt + 1, (kt + 1) & 1);
            CP_COMMIT();
            CP_WAIT(1);
        } else {
            CP_WAIT(0);
        }
        __syncthreads();

        const float* Ksc = smf + (kt & 1) * TILE_F;
        const float* Vsc = Ksc + 64 * FKS_ST;

        float sf[8][4];
#pragma unroll
        for (int nt = 0; nt < 8; ++nt)
#pragma unroll
            for (int r = 0; r < 4; ++r) sf[nt][r] = 0.f;
#pragma unroll
        for (int nt = 0; nt < 8; ++nt) {
            const float* krow = Ksc + (nt * 8 + group) * FKS_ST;
#pragma unroll
            for (int ks = 0; ks < 8; ++ks) {
                const uint32_t b0 = f_as_u(krow[ks * 8 + tig]);
                const uint32_t b1 = f_as_u(krow[ks * 8 + tig + 4]);
                MMA_TF32(sf[nt], qf[ks], b0, b1);
            }
        }

        float mx0 = -1e30f, mx1 = -1e30f;
#pragma unroll
        for (int nt = 0; nt < 8; ++nt) {
            mx0 = fmaxf(mx0, fmaxf(sf[nt][0], sf[nt][1]));
            mx1 = fmaxf(mx1, fmaxf(sf[nt][2], sf[nt][3]));
        }
        mx0 = fmaxf(mx0, __shfl_xor_sync(0xffffffffu, mx0, 1));
        mx0 = fmaxf(mx0, __shfl_xor_sync(0xffffffffu, mx0, 2));
        mx1 = fmaxf(mx1, __shfl_xor_sync(0xffffffffu, mx1, 1));
        mx1 = fmaxf(mx1, __shfl_xor_sync(0xffffffffu, mx1, 2));
        const float M0 = fmaxf(m0, mx0), M1 = fmaxf(m1, mx1);
        const float al0 = __expf(m0 - M0), al1 = __expf(m1 - M1);
        float s0 = 0.f, s1 = 0.f;
#pragma unroll
        for (int nt = 0; nt < 8; ++nt) {
            sf[nt][0] = __expf(sf[nt][0] - M0);
            sf[nt][1] = __expf(sf[nt][1] - M0);
            sf[nt][2] = __expf(sf[nt][2] - M1);
            sf[nt][3] = __expf(sf[nt][3] - M1);
            s0 += sf[nt][0] + sf[nt][1];
            s1 += sf[nt][2] + sf[nt][3];
        }
        s0 += __shfl_xor_sync(0xffffffffu, s0, 1);
        s0 += __shfl_xor_sync(0xffffffffu, s0, 2);
        s1 += __shfl_xor_sync(0xffffffffu, s1, 1);
        s1 += __shfl_xor_sync(0xffffffffu, s1, 2);
        l0 = l0 * al0 + s0;  m0 = M0;
        l1 = l1 * al1 + s1;  m1 = M1;

#pragma unroll
        for (int nt = 0; nt < 8; ++nt) {
            of[nt][0] *= al0; of[nt][1] *= al0;
            of[nt][2] *= al1; of[nt][3] *= al1;
        }
#pragma unroll
        for (int ks = 0; ks < 8; ++ks) {
            const float a00 = __shfl_sync(0xffffffffu, sf[ks][0], src0);
            const float a01 = __shfl_sync(0xffffffffu, sf[ks][1], src0);
            const float a10 = __shfl_sync(0xffffffffu, sf[ks][2], src0);
            const float a11 = __shfl_sync(0xffffffffu, sf[ks][3], src0);
            const float a20 = __shfl_sync(0xffffffffu, sf[ks][0], src2);
            const float a21 = __shfl_sync(0xffffffffu, sf[ks][1], src2);
            const float a30 = __shfl_sync(0xffffffffu, sf[ks][2], src2);
            const float a31 = __shfl_sync(0xffffffffu, sf[ks][3], src2);
            uint32_t pa[4];
            pa[0] = f2tf(odd ? a01 : a00);
            pa[1] = f2tf(odd ? a11 : a10);
            pa[2] = f2tf(odd ? a21 : a20);
            pa[3] = f2tf(odd ? a31 : a30);
            const float* v0row = Vsc + (ks * 8 + tig) * FVS_ST;
            const float* v1row = Vsc + (ks * 8 + tig + 4) * FVS_ST;
#pragma unroll
            for (int nt = 0; nt < 8; ++nt) {
                const uint32_t b0 = f_as_u(v0row[nt * 8 + group]);
                const uint32_t b1 = f_as_u(v1row[nt * 8 + group]);
                MMA_TF32(of[nt], pa, b0, b1);
            }
        }
        __syncthreads();
    }

    // epilogue: write O directly as bf16 hi/lo pairs
    const float i0 = 1.f / l0, i1 = 1.f / l1;
    const size_t base0 = ((size_t)(b * S_ + q0 + wb + group)) * Dm + h * DK_;
    const size_t base1 = ((size_t)(b * S_ + q0 + wb + group + 8)) * Dm + h * DK_;
#pragma unroll
    for (int nt = 0; nt < 8; ++nt) {
        const int col = nt * 8 + tig * 2;
        const float v0 = of[nt][0] * i0, v1 = of[nt][1] * i0;
        const float v2 = of[nt][2] * i1, v3 = of[nt][3] * i1;
        *(uint32_t*)(OH + base0 + col) = pack_hi2(v0, v1);
        *(uint32_t*)(OL + base0 + col) = pack_lo2(v0, v1);
        *(uint32_t*)(OH + base1 + col) = pack_hi2(v2, v3);
        *(uint32_t*)(OL + base1 + col) = pack_lo2(v2, v3);
    }
}

// ===========================================================================
extern "C" void kernel_launch(void* const* d_in, const int* in_sizes, int n_in,
                              void* d_out, int out_size) {
    const float* x  = (const float*)d_in[0];
    const float* Wq = (const float*)d_in[1];
    const float* Wk = (const float*)d_in[2];
    const float* Wv = (const float*)d_in[3];
    const float* Wo = (const float*)d_in[4];
    float* out = (float*)d_out;

    float *Qp, *Kp, *Vp;
    __nv_bfloat16 *xh, *xl, *oh, *ol, *wh, *wl;
    cudaGetSymbolAddress((void**)&Qp, g_Q);
    cudaGetSymbolAddress((void**)&Kp, g_K);
    cudaGetSymbolAddress((void**)&Vp, g_V);
    cudaGetSymbolAddress((void**)&xh, g_xh);
    cudaGetSymbolAddress((void**)&xl, g_xl);
    cudaGetSymbolAddress((void**)&oh, g_oh);
    cudaGetSymbolAddress((void**)&ol, g_ol);
    cudaGetSymbolAddress((void**)&wh, g_wh);
    cudaGetSymbolAddress((void**)&wl, g_wl);

    cudaFuncSetAttribute(gemm_qkv, cudaFuncAttributeMaxDynamicSharedMemorySize,
                         GEMM_SMEM);
    cudaFuncSetAttribute(gemm_sp, cudaFuncAttributeMaxDynamicSharedMemorySize,
                         GEMM_SMEM);
    cudaFuncSetAttribute(flash_tf32, cudaFuncAttributeMaxDynamicSharedMemorySize,
                         ATT_SMEM);

    const size_t WN = (size_t)Dm * Dm;  // 1M elements per W
    const int n4x = (Mrows * Dm) / 4;   // 1M float4
    const int n4w = (int)(WN / 4);      // 256K float4

    split_bf16<<<(n4x + 255) / 256, 256>>>(x, xh, xl, n4x);
    split_w4<<<(4 * n4w + 255) / 256, 256>>>(Wq, Wk, Wv, Wo, wh, wl, n4w);

    const dim3 gQKV(Dm / 128, Mrows / 128, 3);    // (8, 32, 3)
    gemm_qkv<<<gQKV, 256, GEMM_SMEM>>>(xh, xl, wh, wl, Qp, Kp, Vp);

    const dim3 gAttn(S_ / 128, H_, B_);           // (16, 16, 2)
    flash_tf32<<<gAttn, 256, ATT_SMEM>>>(Qp, Kp, Vp, oh, ol);

    const dim3 gProj(Dm / 128, Mrows / 128);      // (8, 32)
    gemm_sp<<<gProj, 256, GEMM_SMEM>>>(oh, ol, wh + 3 * WN, wl + 3 * WN, out);
}

// round 9
// speedup vs baseline: 4.1583x; 1.1039x over previous
#include <cuda_runtime.h>
#include <cuda_bf16.h>
#include <cstdint>

// ===========================================================================
// Problem constants
// ===========================================================================
constexpr int B_   = 2;
constexpr int S_   = 2048;
constexpr int Dm   = 1024;
constexpr int H_   = 16;
constexpr int DK_  = 64;
constexpr int Mrows = B_ * S_;        // 4096
constexpr float ATT_SCALE = 0.125f;   // 1/sqrt(64)

// Scratch (allocation-free: __device__ globals)
__device__ float g_Q[(size_t)Mrows * Dm];
__device__ float g_K[(size_t)Mrows * Dm];
__device__ float g_V[(size_t)Mrows * Dm];
__device__ __nv_bfloat16 g_xh[(size_t)Mrows * Dm];
__device__ __nv_bfloat16 g_xl[(size_t)Mrows * Dm];
__device__ __nv_bfloat16 g_oh[(size_t)Mrows * Dm];
__device__ __nv_bfloat16 g_ol[(size_t)Mrows * Dm];
__device__ __nv_bfloat16 g_wh[(size_t)4 * Dm * Dm];
__device__ __nv_bfloat16 g_wl[(size_t)4 * Dm * Dm];

// ===========================================================================
// mma.sync / ldmatrix / cp.async helpers (legacy tensor path, sm_103 base)
// ===========================================================================
#define MMA_BF16(c, a, b0, b1)                                              \
    asm volatile(                                                           \
        "mma.sync.aligned.m16n8k16.row.col.f32.bf16.bf16.f32 "              \
        "{%0,%1,%2,%3},{%4,%5,%6,%7},{%8,%9},{%0,%1,%2,%3};"                \
        : "+f"((c)[0]), "+f"((c)[1]), "+f"((c)[2]), "+f"((c)[3])            \
        : "r"((a)[0]), "r"((a)[1]), "r"((a)[2]), "r"((a)[3]),               \
          "r"(b0), "r"(b1))

#define MMA_TF32(c, a, b0, b1)                                              \
    asm volatile(                                                           \
        "mma.sync.aligned.m16n8k8.row.col.f32.tf32.tf32.f32 "               \
        "{%0,%1,%2,%3},{%4,%5,%6,%7},{%8,%9},{%0,%1,%2,%3};"                \
        : "+f"((c)[0]), "+f"((c)[1]), "+f"((c)[2]), "+f"((c)[3])            \
        : "r"((a)[0]), "r"((a)[1]), "r"((a)[2]), "r"((a)[3]),               \
          "r"(b0), "r"(b1))

// tf32 MMA where A comes in as float regs (accumulator reinterpret)
#define MMA_TF32F(c, a0, a1, a2, a3, b0, b1)                                \
    asm volatile(                                                           \
        "mma.sync.aligned.m16n8k8.row.col.f32.tf32.tf32.f32 "               \
        "{%0,%1,%2,%3},{%4,%5,%6,%7},{%8,%9},{%0,%1,%2,%3};"                \
        : "+f"((c)[0]), "+f"((c)[1]), "+f"((c)[2]), "+f"((c)[3])            \
        : "r"(a0), "r"(a1), "r"(a2), "r"(a3), "r"(b0), "r"(b1))

#define LDSM4(R, addr)                                                      \
    asm volatile("ldmatrix.sync.aligned.m8n8.x4.shared.b16 "                \
                 "{%0,%1,%2,%3}, [%4];"                                     \
                 : "=r"((R)[0]), "=r"((R)[1]), "=r"((R)[2]), "=r"((R)[3])   \
                 : "r"(addr))

#define CP_ASYNC16(dst, src)                                                \
    asm volatile("cp.async.cg.shared.global [%0], [%1], 16;"                \
                 :: "r"(dst), "l"(src))
#define CP_COMMIT() asm volatile("cp.async.commit_group;" ::: "memory")
#define CP_WAIT(n)  asm volatile("cp.async.wait_group %0;" :: "n"(n) : "memory")

__device__ __forceinline__ uint32_t smem_u32(const void* p) {
    uint32_t a;
    asm("{ .reg .u64 t; cvta.to.shared.u64 t, %1; cvt.u32.u64 %0, t; }"
        : "=r"(a) : "l"(p));
    return a;
}
__device__ __forceinline__ uint32_t f2tf(float x) {
    uint32_t r;
    asm("cvt.rna.tf32.f32 %0, %1;" : "=r"(r) : "f"(x));
    return r;
}
__device__ __forceinline__ float u2f(uint32_t x) { return __uint_as_float(x); }
__device__ __forceinline__ uint32_t f_as_u(float x) { return __float_as_uint(x); }

__device__ __forceinline__ uint32_t pack_hi2(float x, float y) {
    __nv_bfloat16 hx = __float2bfloat16_rn(x);
    __nv_bfloat16 hy = __float2bfloat16_rn(y);
    return ((uint32_t)__bfloat16_as_ushort(hy) << 16) | __bfloat16_as_ushort(hx);
}
__device__ __forceinline__ uint32_t pack_lo2(float x, float y) {
    __nv_bfloat16 hx = __float2bfloat16_rn(x);
    __nv_bfloat16 hy = __float2bfloat16_rn(y);
    __nv_bfloat16 lx = __float2bfloat16_rn(x - __bfloat162float(hx));
    __nv_bfloat16 ly = __float2bfloat16_rn(y - __bfloat162float(hy));
    return ((uint32_t)__bfloat16_as_ushort(ly) << 16) | __bfloat16_as_ushort(lx);
}

// ===========================================================================
// Pre-split: fp32 -> bf16 hi + bf16 lo
// ===========================================================================
__global__ __launch_bounds__(256) void split_bf16(const float* __restrict__ in,
                                                  __nv_bfloat16* __restrict__ hi,
                                                  __nv_bfloat16* __restrict__ lo,
                                                  int n4) {
    const int i = blockIdx.x * 256 + threadIdx.x;
    if (i >= n4) return;
    float4 v = ((const float4*)in)[i];
    uint2 ph, pl;
    ph.x = pack_hi2(v.x, v.y);  ph.y = pack_hi2(v.z, v.w);
    pl.x = pack_lo2(v.x, v.y);  pl.y = pack_lo2(v.z, v.w);
    ((uint2*)hi)[i] = ph;
    ((uint2*)lo)[i] = pl;
}

__global__ __launch_bounds__(256) void split_w4(const float* __restrict__ w0,
                                                const float* __restrict__ w1,
                                                const float* __restrict__ w2,
                                                const float* __restrict__ w3,
                                                __nv_bfloat16* __restrict__ hi,
                                                __nv_bfloat16* __restrict__ lo,
                                                int n4each) {
    const int i = blockIdx.x * 256 + threadIdx.x;
    if (i >= 4 * n4each) return;
    const int w = i / n4each, j = i - w * n4each;
    const float* src = (w == 0) ? w0 : (w == 1) ? w1 : (w == 2) ? w2 : w3;
    float4 v = ((const float4*)src)[j];
    uint2 ph, pl;
    ph.x = pack_hi2(v.x, v.y);  ph.y = pack_hi2(v.z, v.w);
    pl.x = pack_lo2(v.x, v.y);  pl.y = pack_lo2(v.z, v.w);
    ((uint2*)hi)[i] = ph;
    ((uint2*)lo)[i] = pl;
}

// ===========================================================================
// GEMM core: 128x128 tile, bf16 3-term split, 3-stage cp.async pipeline,
// ONE __syncthreads per k-chunk (wait -> barrier -> issue(kc+2) -> compute).
// ===========================================================================
constexpr int NKC = Dm / 32;          // 32 k-chunks
constexpr int GEMM_SMEM = 3 * 32768;  // 98304

__device__ __forceinline__ uint32_t swaddr(uint32_t base, int row, int ch) {
    return base + row * 64 + (((ch) ^ ((row >> 1) & 3)) << 4);
}

__device__ __forceinline__ void gemm_core(
        const __nv_bfloat16* __restrict__ Ah, const __nv_bfloat16* __restrict__ Al,
        const __nv_bfloat16* __restrict__ Bh, const __nv_bfloat16* __restrict__ Bl,
        float* __restrict__ C, int row0, int col0, uint32_t smb) {
    const int tid = threadIdx.x;
    const int lane = tid & 31;
    const int wid = tid >> 5;
    const int wm = (wid >> 2) * 64;
    const int wn = (wid & 3) * 32;
    const int group = lane >> 2, tig = lane & 3;

    float c[4][4][4];
#pragma unroll
    for (int i = 0; i < 4; ++i)
#pragma unroll
        for (int j = 0; j < 4; ++j)
#pragma unroll
            for (int r = 0; r < 4; ++r) c[i][j][r] = 0.f;

    auto issue = [&](int kc, int s) {
        const uint32_t base = smb + s * 32768;
#pragma unroll
        for (int i = 0; i < 2; ++i) {
            const int cidx = tid + i * 256;
            const int row = cidx >> 2, ch = cidx & 3;
            const size_t ga = (size_t)(row0 + row) * Dm + kc * 32 + ch * 8;
            const size_t gb = (size_t)(col0 + row) * Dm + kc * 32 + ch * 8;
            CP_ASYNC16(swaddr(base,         row, ch), Ah + ga);
            CP_ASYNC16(swaddr(base + 8192,  row, ch), Al + ga);
            CP_ASYNC16(swaddr(base + 16384, row, ch), Bh + gb);
            CP_ASYNC16(swaddr(base + 24576, row, ch), Bl + gb);
        }
    };

    issue(0, 0); CP_COMMIT();
    issue(1, 1); CP_COMMIT();

    for (int kc = 0; kc < NKC; ++kc) {
        if (kc + 1 < NKC) { CP_WAIT(1); } else { CP_WAIT(0); }
        __syncthreads();
        if (kc + 2 < NKC) {
            issue(kc + 2, (kc + 2) % 3);
            CP_COMMIT();
        }

        const uint32_t sA = smb + (kc % 3) * 32768;
        const uint32_t sB = sA + 16384;
#pragma unroll
        for (int u = 0; u < 2; ++u) {
            uint32_t bh[8], bl8[8];
#pragma unroll
            for (int p = 0; p < 2; ++p) {
                const int nrow = wn + p * 16 + (lane & 15);
                const int chL = u * 2 + (lane >> 4);
                LDSM4(bh + p * 4,  swaddr(sB,        nrow, chL));
                LDSM4(bl8 + p * 4, swaddr(sB + 8192, nrow, chL));
            }
#pragma unroll
            for (int mt = 0; mt < 4; ++mt) {
                const int mrow = wm + mt * 16 + (lane & 15);
                const int chL = u * 2 + (lane >> 4);
                uint32_t ah[4], alr[4];
                LDSM4(ah,  swaddr(sA,        mrow, chL));
                LDSM4(alr, swaddr(sA + 8192, mrow, chL));
#pragma unroll
                for (int j = 0; j < 4; ++j) {
                    const int p = j >> 1, q = j & 1;
                    MMA_BF16(c[mt][j], ah,  bh[p * 4 + q],  bh[p * 4 + q + 2]);
                    MMA_BF16(c[mt][j], ah,  bl8[p * 4 + q], bl8[p * 4 + q + 2]);
                    MMA_BF16(c[mt][j], alr, bh[p * 4 + q],  bh[p * 4 + q + 2]);
                }
            }
        }
    }

#pragma unroll
    for (int mt = 0; mt < 4; ++mt) {
#pragma unroll
        for (int j = 0; j < 4; ++j) {
            const int r = row0 + wm + mt * 16 + group;
            const int col = col0 + wn + j * 8 + tig * 2;
            float2 v0 = make_float2(c[mt][j][0], c[mt][j][1]);
            float2 v1 = make_float2(c[mt][j][2], c[mt][j][3]);
            *(float2*)(C + (size_t)r * Dm + col)       = v0;
            *(float2*)(C + (size_t)(r + 8) * Dm + col) = v1;
        }
    }
}

__global__ __launch_bounds__(256, 2) void gemm_qkv(
        const __nv_bfloat16* __restrict__ xh, const __nv_bfloat16* __restrict__ xl,
        const __nv_bfloat16* __restrict__ Wh, const __nv_bfloat16* __restrict__ Wl,
        float* __restrict__ Q, float* __restrict__ K, float* __restrict__ V) {
    extern __shared__ char smc[];
    const int z = blockIdx.z;
    const size_t WN = (size_t)Dm * Dm;
    float* C = (z == 0) ? Q : (z == 1) ? K : V;
    gemm_core(xh, xl, Wh + z * WN, Wl + z * WN, C,
              blockIdx.y * 128, blockIdx.x * 128, smem_u32(smc));
}

__global__ __launch_bounds__(256, 2) void gemm_sp(
        const __nv_bfloat16* __restrict__ Ah, const __nv_bfloat16* __restrict__ Al,
        const __nv_bfloat16* __restrict__ Bh, const __nv_bfloat16* __restrict__ Bl,
        float* __restrict__ C) {
    extern __shared__ char smc[];
    gemm_core(Ah, Al, Bh, Bl, C, blockIdx.y * 128, blockIdx.x * 128,
              smem_u32(smc));
}

// ===========================================================================
// Flash attention, tf32 mma.sync, 3-stage cp.async, ONE barrier per tile.
// P relayout trick: S n-col 2t serves as PV k-index t, col 2t+1 as t+4.
// => C-fragment {c0,c2,c1,c3} is directly the PV A-fragment (no shuffles);
//    V rows read permuted: b0 <- row 8ks+2*tig, b1 <- row 8ks+2*tig+1.
// Strides: K 68 (banks 4g+t, conflict-free), V 68 (permuted banks 8t+4+g,
// conflict-free). Stage = (64*68)*2 floats = 34816 B; 3 stages = 104448 B.
// ===========================================================================
constexpr int FST = 68;
constexpr int FTILE_B = 64 * FST * 4 * 2;          // 34816 bytes per stage
constexpr int ATT_SMEM = 3 * FTILE_B;              // 104448
constexpr int NT_ = S_ / 64;                       // 32 tiles

__global__ __launch_bounds__(256, 2) void flash_tf32(
        const float* __restrict__ Q, const float* __restrict__ K,
        const float* __restrict__ V,
        __nv_bfloat16* __restrict__ OH, __nv_bfloat16* __restrict__ OL) {
    extern __shared__ float smf[];
    const uint32_t smb = smem_u32(smf);

    const int tid = threadIdx.x;
    const int lane = tid & 31;
    const int wid = tid >> 5;
    const int group = lane >> 2, tig = lane & 3;
    const int q0 = blockIdx.x * 128;
    const int h = blockIdx.y;
    const int b = blockIdx.z;
    const int wb = wid * 16;

    const float* Kb = K + ((size_t)(b * S_)) * Dm + h * DK_;
    const float* Vb = V + ((size_t)(b * S_)) * Dm + h * DK_;

    auto issue = [&](int kt, int s) {
        const uint32_t kbase = smb + s * FTILE_B;
        const uint32_t vbase = kbase + 64 * FST * 4;
#pragma unroll
        for (int i = 0; i < 4; ++i) {
            const int id = tid + i * 256;
            const int r = id >> 4, ch = id & 15;
            const size_t g = (size_t)(kt * 64 + r) * Dm + ch * 4;
            CP_ASYNC16(kbase + r * (FST * 4) + ch * 16, Kb + g);
            CP_ASYNC16(vbase + r * (FST * 4) + ch * 16, Vb + g);
        }
    };

    issue(0, 0); CP_COMMIT();
    issue(1, 1); CP_COMMIT();

    uint32_t qf[8][4];
    {
        const float* Qb = Q + ((size_t)(b * S_ + q0 + wb)) * Dm + h * DK_;
#pragma unroll
        for (int ks = 0; ks < 8; ++ks) {
            const int k0 = ks * 8 + tig;
            qf[ks][0] = f2tf(Qb[(size_t)group * Dm + k0] * ATT_SCALE);
            qf[ks][1] = f2tf(Qb[(size_t)(group + 8) * Dm + k0] * ATT_SCALE);
            qf[ks][2] = f2tf(Qb[(size_t)group * Dm + k0 + 4] * ATT_SCALE);
            qf[ks][3] = f2tf(Qb[(size_t)(group + 8) * Dm + k0 + 4] * ATT_SCALE);
        }
    }

    float of[8][4];
#pragma unroll
    for (int nt = 0; nt < 8; ++nt)
#pragma unroll
        for (int r = 0; r < 4; ++r) of[nt][r] = 0.f;
    float m0 = -1e30f, m1 = -1e30f, l0 = 0.f, l1 = 0.f;

    for (int kt = 0; kt < NT_; ++kt) {
        if (kt + 1 < NT_) { CP_WAIT(1); } else { CP_WAIT(0); }
        __syncthreads();
        if (kt + 2 < NT_) {
            issue(kt + 2, (kt + 2) % 3);
            CP_COMMIT();
        }

        const float* Ksc = smf + (kt % 3) * (FTILE_B / 4);
        const float* Vsc = Ksc + 64 * FST;

        // S = Q K^T (16 x 64 per warp)
        float sf[8][4];
#pragma unroll
        for (int nt = 0; nt < 8; ++nt)
#pragma unroll
            for (int r = 0; r < 4; ++r) sf[nt][r] = 0.f;
#pragma unroll
        for (int nt = 0; nt < 8; ++nt) {
            const float* krow = Ksc + (nt * 8 + group) * FST;
#pragma unroll
            for (int ks = 0; ks < 8; ++ks) {
                const uint32_t b0 = f_as_u(krow[ks * 8 + tig]);
                const uint32_t b1 = f_as_u(krow[ks * 8 + tig + 4]);
                MMA_TF32(sf[nt], qf[ks], b0, b1);
            }
        }

        // online softmax on fragments (column order irrelevant)
        float mx0 = -1e30f, mx1 = -1e30f;
#pragma unroll
        for (int nt = 0; nt < 8; ++nt) {
            mx0 = fmaxf(mx0, fmaxf(sf[nt][0], sf[nt][1]));
            mx1 = fmaxf(mx1, fmaxf(sf[nt][2], sf[nt][3]));
        }
        mx0 = fmaxf(mx0, __shfl_xor_sync(0xffffffffu, mx0, 1));
        mx0 = fmaxf(mx0, __shfl_xor_sync(0xffffffffu, mx0, 2));
        mx1 = fmaxf(mx1, __shfl_xor_sync(0xffffffffu, mx1, 1));
        mx1 = fmaxf(mx1, __shfl_xor_sync(0xffffffffu, mx1, 2));
        const float M0 = fmaxf(m0, mx0), M1 = fmaxf(m1, mx1);
        const float al0 = __expf(m0 - M0), al1 = __expf(m1 - M1);
        float s0 = 0.f, s1 = 0.f;
#pragma unroll
        for (int nt = 0; nt < 8; ++nt) {
            sf[nt][0] = __expf(sf[nt][0] - M0);
            sf[nt][1] = __expf(sf[nt][1] - M0);
            sf[nt][2] = __expf(sf[nt][2] - M1);
            sf[nt][3] = __expf(sf[nt][3] - M1);
            s0 += sf[nt][0] + sf[nt][1];
            s1 += sf[nt][2] + sf[nt][3];
        }
        s0 += __shfl_xor_sync(0xffffffffu, s0, 1);
        s0 += __shfl_xor_sync(0xffffffffu, s0, 2);
        s1 += __shfl_xor_sync(0xffffffffu, s1, 1);
        s1 += __shfl_xor_sync(0xffffffffu, s1, 2);
        l0 = l0 * al0 + s0;  m0 = M0;
        l1 = l1 * al1 + s1;  m1 = M1;

        // rescale O, then O += P V : C-fragment directly reused as A-fragment
#pragma unroll
        for (int nt = 0; nt < 8; ++nt) {
            of[nt][0] *= al0; of[nt][1] *= al0;
            of[nt][2] *= al1; of[nt][3] *= al1;
        }
#pragma unroll
        for (int ks = 0; ks < 8; ++ks) {
            uint32_t pa0 = f2tf(sf[ks][0]);   // A[g][t]     = C[g][2t]
            uint32_t pa1 = f2tf(sf[ks][2]);   // A[g+8][t]   = C[g+8][2t]
            uint32_t pa2 = f2tf(sf[ks][1]);   // A[g][t+4]   = C[g][2t+1]
            uint32_t pa3 = f2tf(sf[ks][3]);   // A[g+8][t+4] = C[g+8][2t+1]
            const float* v0row = Vsc + (ks * 8 + 2 * tig) * FST;      // key col 2t
            const float* v1row = Vsc + (ks * 8 + 2 * tig + 1) * FST;  // key col 2t+1
#pragma unroll
            for (int nt = 0; nt < 8; ++nt) {
                const uint32_t b0 = f_as_u(v0row[nt * 8 + group]);
                const uint32_t b1 = f_as_u(v1row[nt * 8 + group]);
                MMA_TF32F(of[nt], pa0, pa1, pa2, pa3, b0, b1);
            }
        }
    }

    // epilogue: write O directly as bf16 hi/lo pairs
    const float i0 = 1.f / l0, i1 = 1.f / l1;
    const size_t base0 = ((size_t)(b * S_ + q0 + wb + group)) * Dm + h * DK_;
    const size_t base1 = ((size_t)(b * S_ + q0 + wb + group + 8)) * Dm + h * DK_;
#pragma unroll
    for (int nt = 0; nt < 8; ++nt) {
        const int col = nt * 8 + tig * 2;
        const float v0 = of[nt][0] * i0, v1 = of[nt][1] * i0;
        const float v2 = of[nt][2] * i1, v3 = of[nt][3] * i1;
        *(uint32_t*)(OH + base0 + col) = pack_hi2(v0, v1);
        *(uint32_t*)(OL + base0 + col) = pack_lo2(v0, v1);
        *(uint32_t*)(OH + base1 + col) = pack_hi2(v2, v3);
        *(uint32_t*)(OL + base1 + col) = pack_lo2(v2, v3);
    }
}

// ===========================================================================
extern "C" void kernel_launch(void* const* d_in, const int* in_sizes, int n_in,
                              void* d_out, int out_size) {
    const float* x  = (const float*)d_in[0];
    const float* Wq = (const float*)d_in[1];
    const float* Wk = (const float*)d_in[2];
    const float* Wv = (const float*)d_in[3];
    const float* Wo = (const float*)d_in[4];
    float* out = (float*)d_out;

    float *Qp, *Kp, *Vp;
    __nv_bfloat16 *xh, *xl, *oh, *ol, *wh, *wl;
    cudaGetSymbolAddress((void**)&Qp, g_Q);
    cudaGetSymbolAddress((void**)&Kp, g_K);
    cudaGetSymbolAddress((void**)&Vp, g_V);
    cudaGetSymbolAddress((void**)&xh, g_xh);
    cudaGetSymbolAddress((void**)&xl, g_xl);
    cudaGetSymbolAddress((void**)&oh, g_oh);
    cudaGetSymbolAddress((void**)&ol, g_ol);
    cudaGetSymbolAddress((void**)&wh, g_wh);
    cudaGetSymbolAddress((void**)&wl, g_wl);

    cudaFuncSetAttribute(gemm_qkv, cudaFuncAttributeMaxDynamicSharedMemorySize,
                         GEMM_SMEM);
    cudaFuncSetAttribute(gemm_sp, cudaFuncAttributeMaxDynamicSharedMemorySize,
                         GEMM_SMEM);
    cudaFuncSetAttribute(flash_tf32, cudaFuncAttributeMaxDynamicSharedMemorySize,
                         ATT_SMEM);

    const size_t WN = (size_t)Dm * Dm;  // 1M elements per W
    const int n4x = (Mrows * Dm) / 4;   // 1M float4
    const int n4w = (int)(WN / 4);      // 256K float4

    split_bf16<<<(n4x + 255) / 256, 256>>>(x, xh, xl, n4x);
    split_w4<<<(4 * n4w + 255) / 256, 256>>>(Wq, Wk, Wv, Wo, wh, wl, n4w);

    const dim3 gQKV(Dm / 128, Mrows / 128, 3);    // (8, 32, 3)
    gemm_qkv<<<gQKV, 256, GEMM_SMEM>>>(xh, xl, wh, wl, Qp, Kp, Vp);

    const dim3 gAttn(S_ / 128, H_, B_);           // (16, 16, 2)
    flash_tf32<<<gAttn, 256, ATT_SMEM>>>(Qp, Kp, Vp, oh, ol);

    const dim3 gProj(Dm / 128, Mrows / 128);      // (8, 32)
    gemm_sp<<<gProj, 256, GEMM_SMEM>>>(oh, ol, wh + 3 * WN, wl + 3 * WN, out);
}